// round 14
// baseline (speedup 1.0000x reference)
#include <cuda_runtime.h>
#include <cuda_bf16.h>
#include <cstdint>

#define B 4
#define S 2048
#define H 4
#define DH 48
#define D 192
#define NEG_INF -1000000000.0f

// Scratch
__device__ float g_ctx[B*S*D];
__device__ float g_Linv[B*H*S];
__device__ float g_WT[4][D*D];                 // pre-transposed weights [k][j]
__device__ __nv_bfloat16 g_qh[B*H*S*DH];
__device__ __nv_bfloat16 g_ql[B*H*S*DH];
__device__ __nv_bfloat16 g_kh[B*H*S*DH];
__device__ __nv_bfloat16 g_kl[B*H*S*DH];
__device__ __nv_bfloat16 g_vh[B*H*S*DH];
__device__ __nv_bfloat16 g_vl[B*H*S*DH];
// E stored j-PERMUTED (fragment-native): within each 32-j group,
// actual a = 2p + 8t + u  <->  virtual v = 8p + 2t + u.
__device__ __nv_bfloat16 g_Eh[(size_t)B*H*S*S];
__device__ __nv_bfloat16 g_El[(size_t)B*H*S*S];

// ---------- packed fp32x2 helpers ----------
__device__ __forceinline__ unsigned long long pack2(float x, float y) {
    unsigned long long r;
    asm("mov.b64 %0, {%1,%2};" : "=l"(r) : "f"(x), "f"(y));
    return r;
}
__device__ __forceinline__ void unpack2(unsigned long long v, float& x, float& y) {
    asm("mov.b64 {%0,%1}, %2;" : "=f"(x), "=f"(y) : "l"(v));
}
__device__ __forceinline__ void ffma2(unsigned long long& d, unsigned long long a, unsigned long long b) {
    asm("fma.rn.f32x2 %0, %1, %2, %0;" : "+l"(d) : "l"(a), "l"(b));
}

// ---------- fast exp on the FMA pipe ----------
__device__ __forceinline__ float fexp(float x) {
    float y = fmaxf(x * 1.44269504f, -126.0f);
    float t = y + 12582912.0f;
    float f = y - (t - 12582912.0f);
    int   e = __float_as_int(t) - 0x4B400000;
    float s = __int_as_float((e + 127) << 23);
    float p =              1.3333558e-3f;
    p = fmaf(p, f, 9.6181291e-3f);
    p = fmaf(p, f, 5.5504109e-2f);
    p = fmaf(p, f, 2.4022651e-1f);
    p = fmaf(p, f, 6.9314718e-1f);
    p = fmaf(p, f, 1.0f);
    return p * s;
}

// ---------- cp.async helpers ----------
__device__ __forceinline__ void cp16(uint32_t saddr, const void* gptr) {
    asm volatile("cp.async.cg.shared.global [%0], [%1], 16;" :: "r"(saddr), "l"(gptr));
}
__device__ __forceinline__ void cp_commit() { asm volatile("cp.async.commit_group;"); }
__device__ __forceinline__ void cp_wait2()  { asm volatile("cp.async.wait_group 2;"); }
__device__ __forceinline__ void cp_wait1()  { asm volatile("cp.async.wait_group 1;"); }
__device__ __forceinline__ void cp_wait0()  { asm volatile("cp.async.wait_group 0;"); }
__device__ __forceinline__ uint32_t cvta_s(const void* p) {
    return (uint32_t)__cvta_generic_to_shared(p);
}

// ---------- mma.sync / ldmatrix helpers ----------
__device__ __forceinline__ void ldsm4(uint32_t addr, uint32_t* r) {
    asm volatile("ldmatrix.sync.aligned.m8n8.x4.shared.b16 {%0,%1,%2,%3}, [%4];"
                 : "=r"(r[0]), "=r"(r[1]), "=r"(r[2]), "=r"(r[3]) : "r"(addr));
}
__device__ __forceinline__ void ldsm4t(uint32_t addr, uint32_t* r) {
    asm volatile("ldmatrix.sync.aligned.m8n8.x4.trans.shared.b16 {%0,%1,%2,%3}, [%4];"
                 : "=r"(r[0]), "=r"(r[1]), "=r"(r[2]), "=r"(r[3]) : "r"(addr));
}
__device__ __forceinline__ void ldsm2t(uint32_t addr, uint32_t* r) {
    asm volatile("ldmatrix.sync.aligned.m8n8.x2.trans.shared.b16 {%0,%1}, [%2];"
                 : "=r"(r[0]), "=r"(r[1]) : "r"(addr));
}
__device__ __forceinline__ void mma16816(float* c, const uint32_t* a, const uint32_t* b) {
    asm volatile("mma.sync.aligned.m16n8k16.row.col.f32.bf16.bf16.f32 "
                 "{%0,%1,%2,%3}, {%4,%5,%6,%7}, {%8,%9}, {%0,%1,%2,%3};"
                 : "+f"(c[0]), "+f"(c[1]), "+f"(c[2]), "+f"(c[3])
                 : "r"(a[0]), "r"(a[1]), "r"(a[2]), "r"(a[3]), "r"(b[0]), "r"(b[1]));
}

// ---------- weight transpose ----------
__global__ void transpose_w(const float* __restrict__ W0, const float* __restrict__ W1,
                            const float* __restrict__ W2, const float* __restrict__ W3) {
    __shared__ float tile[32][33];
    const float* W = (blockIdx.z == 0) ? W0 : (blockIdx.z == 1) ? W1 : (blockIdx.z == 2) ? W2 : W3;
    float* WT = g_WT[blockIdx.z];
    int x = blockIdx.x*32 + threadIdx.x;
    int y = blockIdx.y*32 + threadIdx.y;
    #pragma unroll
    for (int j = 0; j < 32; j += 8)
        tile[threadIdx.y + j][threadIdx.x] = W[(y + j)*D + x];
    __syncthreads();
    int x2 = blockIdx.y*32 + threadIdx.x;
    int y2 = blockIdx.x*32 + threadIdx.y;
    #pragma unroll
    for (int j = 0; j < 32; j += 8)
        WT[(y2 + j)*D + x2] = tile[threadIdx.x][threadIdx.y + j];
}

// ---------- projection core ----------
template<bool BF16OUT>
__device__ __forceinline__ void proj_core(const float* __restrict__ X,
                                          const float* __restrict__ WT,
                                          float* __restrict__ Yf,
                                          __nv_bfloat16* __restrict__ Yh,
                                          __nv_bfloat16* __restrict__ Yl,
                                          int r0) {
    __shared__ float sXT[192*33];
    const int tid = threadIdx.x;
    const int w = tid >> 5, lane = tid & 31;

    #pragma unroll
    for (int k = 0; k < 12; k++) {
        int idx = tid + k*128;
        int r = idx / 48, c = idx % 48;
        float4 v = *reinterpret_cast<const float4*>(X + (size_t)(r0 + r)*D + 4*c);
        sXT[(4*c+0)*33 + r] = v.x;
        sXT[(4*c+1)*33 + r] = v.y;
        sXT[(4*c+2)*33 + r] = v.z;
        sXT[(4*c+3)*33 + r] = v.w;
    }
    __syncthreads();

    unsigned long long acc[8][3];
    #pragma unroll
    for (int i = 0; i < 8; i++)
        #pragma unroll
        for (int p = 0; p < 3; p++) acc[i][p] = 0ull;

    #pragma unroll 2
    for (int k = 0; k < 192; k++) {
        const unsigned long long* wrow =
            reinterpret_cast<const unsigned long long*>(WT + k*D + lane*6);
        unsigned long long w0 = wrow[0], w1 = wrow[1], w2 = wrow[2];
        #pragma unroll
        for (int i = 0; i < 8; i++) {
            float xv = sXT[k*33 + w*8 + i];
            unsigned long long x2 = pack2(xv, xv);
            ffma2(acc[i][0], x2, w0);
            ffma2(acc[i][1], x2, w1);
            ffma2(acc[i][2], x2, w2);
        }
    }
    #pragma unroll
    for (int i = 0; i < 8; i++) {
        const int row = r0 + w*8 + i;      // b*S + s
        if (BF16OUT) {
            const int bb = row >> 11, s = row & 2047;
            const int hh = lane >> 3, c0 = (lane & 7)*6;
            size_t base = ((size_t)(bb*H + hh)*S + s)*DH + c0;
            #pragma unroll
            for (int m = 0; m < 3; m++) {
                float x, y; unpack2(acc[i][m], x, y);
                __nv_bfloat16 hx = __float2bfloat16(x);
                __nv_bfloat16 hy = __float2bfloat16(y);
                float lx = x - __bfloat162float(hx);
                float ly = y - __bfloat162float(hy);
                __nv_bfloat162 hv; hv.x = hx; hv.y = hy;
                __nv_bfloat162 lv; lv.x = __float2bfloat16(lx); lv.y = __float2bfloat16(ly);
                *reinterpret_cast<__nv_bfloat162*>(Yh + base + 2*m) = hv;
                *reinterpret_cast<__nv_bfloat162*>(Yl + base + 2*m) = lv;
            }
        } else {
            unsigned long long* dst =
                reinterpret_cast<unsigned long long*>(Yf + (size_t)row*D + lane*6);
            dst[0] = acc[i][0]; dst[1] = acc[i][1]; dst[2] = acc[i][2];
        }
    }
}

__global__ __launch_bounds__(128, 4) void proj3_kernel(const float* __restrict__ Xq,
                                                       const float* __restrict__ Xk,
                                                       const float* __restrict__ Xv) {
    const int which = blockIdx.y;
    const int r0 = blockIdx.x * 32;
    if (which == 2)      proj_core<true >(Xv, g_WT[2], nullptr, g_vh, g_vl, r0);
    else if (which == 0) proj_core<true >(Xq, g_WT[0], nullptr, g_qh, g_ql, r0);
    else                 proj_core<true >(Xk, g_WT[1], nullptr, g_kh, g_kl, r0);
}

__global__ __launch_bounds__(128, 4) void proj1_kernel(const float* __restrict__ X,
                                                       float* __restrict__ Y) {
    proj_core<false>(X, g_WT[3], Y, nullptr, nullptr, blockIdx.x * 32);
}

// ============================================================================
// logits_mma (R13: b-major grid, int32 mask, packed permuted E stores, __stcs)
// ============================================================================
#define OFF_QH 0
#define OFF_QL 8192
#define OFF_KH 16384
#define OFF_KL 49152
#define OFF_SUM 81920
#define SMEM_LG (OFF_SUM + 64*4*4)

__global__ __launch_bounds__(256, 2) void logits_mma(const int* __restrict__ gmask,
                                                     const float* __restrict__ gbias) {
    extern __shared__ char smem[];
    const uint32_t sb = cvta_s(smem);
    float (*sums)[4] = reinterpret_cast<float(*)[4]>(smem + OFF_SUM);
    const int tid = threadIdx.x;
    const int warp = tid >> 5, lane = tid & 31;
    const int bh = blockIdx.x;
    const int b  = bh >> 2, h = bh & 3;
    const int q0 = blockIdx.y * 64;
    const int qw = (warp >> 2) * 32;
    const int jw = (warp & 3) * 32;

    {
        const __nv_bfloat16* qh = g_qh + ((size_t)bh*S + q0)*DH;
        const __nv_bfloat16* ql = g_ql + ((size_t)bh*S + q0)*DH;
        #pragma unroll
        for (int k = 0; k < 2; k++) {
            int idx = tid + k*256;
            if (idx < 384) {
                int r = idx / 6, c = idx % 6;
                uint32_t off = r*128 + ((c ^ (r&7))<<4);
                cp16(sb + OFF_QH + off, qh + r*DH + c*8);
                cp16(sb + OFF_QL + off, ql + r*DH + c*8);
            }
        }
        const __nv_bfloat16* kh = g_kh + (size_t)bh*S*DH;
        const __nv_bfloat16* kl = g_kl + (size_t)bh*S*DH;
        #pragma unroll
        for (int k = 0; k < 3; k++) {
            int idx = tid + k*256;
            int r = idx / 6, c = idx % 6;
            uint32_t off = r*128 + ((c ^ (r&7))<<4);
            cp16(sb + OFF_KH + off, kh + r*DH + c*8);
            cp16(sb + OFF_KL + off, kl + r*DH + c*8);
        }
        cp_commit();
    }
    cp_wait0();
    __syncthreads();

    uint32_t ah[2][3][4];
    #pragma unroll
    for (int mi = 0; mi < 2; mi++)
        #pragma unroll
        for (int ks = 0; ks < 3; ks++) {
            int r = qw + mi*16 + (lane & 7) + ((lane >> 3) & 1)*8;
            int c = ks*2 + (lane >> 4);
            ldsm4(sb + OFF_QH + r*128 + ((c ^ (r&7))<<4), ah[mi][ks]);
        }

    float lsum[4] = {0.f, 0.f, 0.f, 0.f};

    for (int jt = 0; jt < 16; jt++) {
        const uint32_t kbH = sb + OFF_KH + (jt & 1)*16384;
        const uint32_t kbL = sb + OFF_KL + (jt & 1)*16384;

        if (jt + 1 < 16) {
            const uint32_t nH = sb + OFF_KH + ((jt+1) & 1)*16384;
            const uint32_t nL = sb + OFF_KL + ((jt+1) & 1)*16384;
            const __nv_bfloat16* kh = g_kh + ((size_t)bh*S + (jt+1)*128)*DH;
            const __nv_bfloat16* kl = g_kl + ((size_t)bh*S + (jt+1)*128)*DH;
            #pragma unroll
            for (int k = 0; k < 3; k++) {
                int idx = tid + k*256;
                int r = idx / 6, c = idx % 6;
                uint32_t off = r*128 + ((c ^ (r&7))<<4);
                cp16(nH + off, kh + r*DH + c*8);
                cp16(nL + off, kl + r*DH + c*8);
            }
            cp_commit();
        }

        float acc[2][4][4];
        #pragma unroll
        for (int mi = 0; mi < 2; mi++)
            #pragma unroll
            for (int nj = 0; nj < 4; nj++)
                #pragma unroll
                for (int p = 0; p < 4; p++) acc[mi][nj][p] = 0.f;

        #pragma unroll
        for (int ks = 0; ks < 3; ks++) {
            uint32_t bhf[2][4], blf[2][4], alf[2][4];
            #pragma unroll
            for (int jj = 0; jj < 2; jj++) {
                int r = jw + jj*16 + (lane & 7) + (lane >> 4)*8;
                int c = ks*2 + ((lane >> 3) & 1);
                uint32_t off = r*128 + ((c ^ (r&7))<<4);
                ldsm4(kbH + off, bhf[jj]);
                ldsm4(kbL + off, blf[jj]);
            }
            #pragma unroll
            for (int mi = 0; mi < 2; mi++) {
                int r = qw + mi*16 + (lane & 7) + ((lane >> 3) & 1)*8;
                int c = ks*2 + (lane >> 4);
                ldsm4(sb + OFF_QL + r*128 + ((c ^ (r&7))<<4), alf[mi]);
            }
            #pragma unroll
            for (int mi = 0; mi < 2; mi++)
                #pragma unroll
                for (int jj = 0; jj < 2; jj++)
                    #pragma unroll
                    for (int sub = 0; sub < 2; sub++) {
                        float* a = acc[mi][jj*2 + sub];
                        mma16816(a, ah[mi][ks], &bhf[jj][sub*2]);
                        mma16816(a, ah[mi][ks], &blf[jj][sub*2]);
                        mma16816(a, alf[mi],    &bhf[jj][sub*2]);
                    }
        }
        __syncthreads();

        const int jbase  = jt*128 + jw + (lane & 3)*2;   // actual j base
        const int jvbase = jt*128 + jw + 8*(lane & 3);   // virtual (permuted)
        #pragma unroll
        for (int mi = 0; mi < 2; mi++)
            #pragma unroll
            for (int h2 = 0; h2 < 2; h2++) {
                const int qrow = q0 + qw + mi*16 + h2*8 + (lane >> 2);
                const int*   mrow = gmask + (size_t)(b*S + qrow)*S + jbase;
                const float* brow = gbias + (size_t)(h*S + qrow)*S + jbase;
                float ls = 0.f;
                uint32_t hw[4], lw[4];
                #pragma unroll
                for (int nj = 0; nj < 4; nj++) {
                    int2   mv = *reinterpret_cast<const int2*>(mrow + nj*8);
                    float2 bv = *reinterpret_cast<const float2*>(brow + nj*8);
                    float e0 = fexp(mv.x ? acc[mi][nj][h2*2+0] + bv.x : NEG_INF);
                    float e1 = fexp(mv.y ? acc[mi][nj][h2*2+1] + bv.y : NEG_INF);
                    __nv_bfloat162 hv;
                    hv.x = __float2bfloat16(e0);
                    hv.y = __float2bfloat16(e1);
                    __nv_bfloat162 lv;
                    lv.x = __float2bfloat16(e0 - __bfloat162float(hv.x));
                    lv.y = __float2bfloat16(e1 - __bfloat162float(hv.y));
                    hw[nj] = *reinterpret_cast<uint32_t*>(&hv);
                    lw[nj] = *reinterpret_cast<uint32_t*>(&lv);
                    ls += e0 + e1;
                }
                uint4 hq; hq.x = hw[0]; hq.y = hw[1]; hq.z = hw[2]; hq.w = hw[3];
                uint4 lq; lq.x = lw[0]; lq.y = lw[1]; lq.z = lw[2]; lq.w = lw[3];
                __stcs(reinterpret_cast<uint4*>(g_Eh + ((size_t)bh*S + qrow)*S + jvbase), hq);
                __stcs(reinterpret_cast<uint4*>(g_El + ((size_t)bh*S + qrow)*S + jvbase), lq);
                lsum[mi*2 + h2] += ls;
            }

        cp_wait0();
    }

    #pragma unroll
    for (int k = 0; k < 4; k++) {
        float v = lsum[k];
        v += __shfl_xor_sync(0xffffffffu, v, 1);
        v += __shfl_xor_sync(0xffffffffu, v, 2);
        if ((lane & 3) == 0)
            sums[qw + (k >> 1)*16 + (k & 1)*8 + (lane >> 2)][warp & 3] = v;
    }
    __syncthreads();
    if (tid < 64) {
        float L = sums[tid][0] + sums[tid][1] + sums[tid][2] + sums[tid][3];
        g_Linv[(size_t)bh*S + q0 + tid] = 1.0f / L;
    }
}

// ============================================================================
// pv_mma: DEPTH-3 cp.async pipeline (3 x 64KB buffers = 226KB smem, just under
// the 227KB cap) — doubles in-flight DMA per SM vs the depth-2 version.
// Buffer reuse distance = 3 stages; end-of-stage __syncthreads orders
// compute(st) before the st+3 load that reuses its buffer.
// ============================================================================
#define PM_OFF_LINV 33792
#define PM_OFF_TILE 34816
#define PM_BUF 65536
#define PM_EH 0
#define PM_EL 16384
#define PM_VH 32768
#define PM_VL 49152
#define SMEM_PV (PM_OFF_TILE + 3*PM_BUF)   // 231424 B = 226 KB

__global__ __launch_bounds__(256, 1) void pv_mma(float* __restrict__ om) {
    extern __shared__ char smem[];
    const uint32_t sb = cvta_s(smem);
    float* sMean  = reinterpret_cast<float*>(smem);                 // [64][132]
    float* sLinvf = reinterpret_cast<float*>(smem + PM_OFF_LINV);   // [4][64]
    const int tid = threadIdx.x;
    const int warp = tid >> 5, lane = tid & 31;
    const int b  = blockIdx.x;
    const int q0 = blockIdx.y * 64;
    const int q0w = (warp >> 1) * 16;
    const int wd  = warp & 1;
    const int cV  = wd * 3;

    {
        int hh = tid >> 6, q = tid & 63;
        sLinvf[tid] = g_Linv[(size_t)(b*H + hh)*S + q0 + q];
    }

    auto load_stage = [&](int st, uint32_t bufb) {
        const int jt = st >> 2, hh = st & 3;
        const int bhl = b*H + hh;
        const __nv_bfloat16* ehp = g_Eh + ((size_t)bhl*S + q0)*S + jt*128;
        const __nv_bfloat16* elp = g_El + ((size_t)bhl*S + q0)*S + jt*128;
        #pragma unroll
        for (int k = 0; k < 4; k++) {
            int idx = tid + k*256;
            int r = idx >> 4, cj = idx & 15;
            uint32_t off = r*256 + ((cj ^ (r&7))<<4);
            cp16(bufb + PM_EH + off, ehp + (size_t)r*S + cj*8);
            cp16(bufb + PM_EL + off, elp + (size_t)r*S + cj*8);
        }
        const __nv_bfloat16* vhp = g_vh + ((size_t)bhl*S + jt*128)*DH;
        const __nv_bfloat16* vlp = g_vl + ((size_t)bhl*S + jt*128)*DH;
        #pragma unroll
        for (int k = 0; k < 3; k++) {
            int idx = tid + k*256;
            int r = idx / 6, c = idx % 6;
            int vr = (r & 96) | (8*((r&7)>>1) + 2*((r>>3)&3) + (r&1));
            uint32_t off = vr*128 + ((c ^ (vr&7))<<4);
            cp16(bufb + PM_VH + off, vhp + r*DH + c*8);
            cp16(bufb + PM_VL + off, vlp + r*DH + c*8);
        }
    };

    // prologue: stages 0 and 1 in flight
    load_stage(0, sb + PM_OFF_TILE + 0*PM_BUF);
    cp_commit();
    load_stage(1, sb + PM_OFF_TILE + 1*PM_BUF);
    cp_commit();
    __syncthreads();

    float acc[4][3][4];
    #pragma unroll
    for (int hh = 0; hh < 4; hh++)
        #pragma unroll
        for (int nt = 0; nt < 3; nt++)
            #pragma unroll
            for (int p = 0; p < 4; p++) acc[hh][nt][p] = 0.f;

    for (int jt = 0; jt < 16; jt++) {
        #pragma unroll
        for (int hh = 0; hh < 4; hh++) {
            const int st = jt*4 + hh;
            if (st + 2 < 64) {
                load_stage(st + 2, sb + PM_OFF_TILE + ((st+2) % 3)*PM_BUF);
                cp_commit();
                cp_wait2();          // stage st's group complete
            } else {
                cp_wait0();
            }
            __syncthreads();
            const uint32_t tb = sb + PM_OFF_TILE + (st % 3)*PM_BUF;
            const char*   tbp = smem + PM_OFF_TILE + (st % 3)*PM_BUF;

            #pragma unroll
            for (int k = 0; k < 4; k++) {
                int idx = tid + k*256;
                int q = idx >> 4, cj = idx & 15;
                uint32_t eoff = q*256 + ((cj ^ (q&7))<<4);
                uint4 uh = *reinterpret_cast<const uint4*>(tbp + PM_EH + eoff);
                uint4 ul = *reinterpret_cast<const uint4*>(tbp + PM_EL + eoff);
                float linv = sLinvf[hh*64 + q];
                float2 f0 = __bfloat1622float2(*reinterpret_cast<__nv_bfloat162*>(&uh.x));
                float2 f1 = __bfloat1622float2(*reinterpret_cast<__nv_bfloat162*>(&uh.y));
                float2 f2 = __bfloat1622float2(*reinterpret_cast<__nv_bfloat162*>(&uh.z));
                float2 f3 = __bfloat1622float2(*reinterpret_cast<__nv_bfloat162*>(&uh.w));
                float2 g0 = __bfloat1622float2(*reinterpret_cast<__nv_bfloat162*>(&ul.x));
                float2 g1 = __bfloat1622float2(*reinterpret_cast<__nv_bfloat162*>(&ul.y));
                float2 g2 = __bfloat1622float2(*reinterpret_cast<__nv_bfloat162*>(&ul.z));
                float2 g3 = __bfloat1622float2(*reinterpret_cast<__nv_bfloat162*>(&ul.w));
                float* mp = sMean + q*132 + cj*8;
                if (hh == 0) {
                    float4 m0, m1;
                    m0.x = (f0.x+g0.x)*linv; m0.y = (f0.y+g0.y)*linv;
                    m0.z = (f1.x+g1.x)*linv; m0.w = (f1.y+g1.y)*linv;
                    m1.x = (f2.x+g2.x)*linv; m1.y = (f2.y+g2.y)*linv;
                    m1.z = (f3.x+g3.x)*linv; m1.w = (f3.y+g3.y)*linv;
                    *reinterpret_cast<float4*>(mp)     = m0;
                    *reinterpret_cast<float4*>(mp + 4) = m1;
                } else {
                    float4 m0 = *reinterpret_cast<float4*>(mp);
                    float4 m1 = *reinterpret_cast<float4*>(mp + 4);
                    m0.x += (f0.x+g0.x)*linv; m0.y += (f0.y+g0.y)*linv;
                    m0.z += (f1.x+g1.x)*linv; m0.w += (f1.y+g1.y)*linv;
                    m1.x += (f2.x+g2.x)*linv; m1.y += (f2.y+g2.y)*linv;
                    m1.z += (f3.x+g3.x)*linv; m1.w += (f3.y+g3.y)*linv;
                    *reinterpret_cast<float4*>(mp)     = m0;
                    *reinterpret_cast<float4*>(mp + 4) = m1;
                }
            }

            #pragma unroll
            for (int ks = 0; ks < 8; ks++) {
                int ra = q0w + (lane & 15);
                int ca = ks*2 + (lane >> 4);
                uint32_t aoff = ra*256 + ((ca ^ (ra&7))<<4);
                uint32_t ahf[4], alf[4];
                ldsm4(tb + PM_EH + aoff, ahf);
                ldsm4(tb + PM_EL + aoff, alf);

                int rb = ks*16 + (lane & 15);
                int cb4 = cV + (lane >> 4);
                uint32_t boff4 = rb*128 + ((cb4 ^ (rb&7))<<4);
                uint32_t bh4[4], bl4[4];
                ldsm4t(tb + PM_VH + boff4, bh4);
                ldsm4t(tb + PM_VL + boff4, bl4);
                int cb2 = cV + 2;
                uint32_t boff2 = rb*128 + ((cb2 ^ (rb&7))<<4);
                uint32_t bh2[2], bl2[2];
                ldsm2t(tb + PM_VH + boff2, bh2);
                ldsm2t(tb + PM_VL + boff2, bl2);

                #pragma unroll
                for (int nt = 0; nt < 2; nt++) {
                    float* a = acc[hh][nt];
                    mma16816(a, ahf, &bh4[nt*2]);
                    mma16816(a, ahf, &bl4[nt*2]);
                    mma16816(a, alf, &bh4[nt*2]);
                }
                {
                    float* a = acc[hh][2];
                    mma16816(a, ahf, bh2);
                    mma16816(a, ahf, bl2);
                    mma16816(a, alf, bh2);
                }
            }

            if (hh == 3) {
                __syncthreads();
                #pragma unroll
                for (int k = 0; k < 8; k++) {
                    int idx = tid + k*256;
                    int q = idx >> 5, c4 = idx & 31;
                    int g = (c4 >> 3) << 5;
                    int r32 = (4*c4) & 31;
                    int v0 = g + 8*((r32 & 7) >> 1) + 2*(r32 >> 3);
                    float2 m0 = *reinterpret_cast<const float2*>(sMean + q*132 + v0);
                    float2 m1 = *reinterpret_cast<const float2*>(sMean + q*132 + v0 + 8);
                    float4 r;
                    r.x = 0.25f*m0.x; r.y = 0.25f*m0.y;
                    r.z = 0.25f*m1.x; r.w = 0.25f*m1.y;
                    *reinterpret_cast<float4*>(om + (size_t)(b*S + q0 + q)*S + jt*128 + c4*4) = r;
                }
            }
            __syncthreads();
        }
    }

    #pragma unroll
    for (int hh = 0; hh < 4; hh++) {
        const int row0 = q0w + (lane >> 2);
        const float l0 = sLinvf[hh*64 + row0];
        const float l1 = sLinvf[hh*64 + row0 + 8];
        #pragma unroll
        for (int nt = 0; nt < 3; nt++) {
            const int col = hh*48 + wd*24 + nt*8 + (lane & 3)*2;
            float2 o0; o0.x = acc[hh][nt][0]*l0; o0.y = acc[hh][nt][1]*l0;
            float2 o1; o1.x = acc[hh][nt][2]*l1; o1.y = acc[hh][nt][3]*l1;
            *reinterpret_cast<float2*>(g_ctx + (size_t)(b*S + q0 + row0)*D + col)     = o0;
            *reinterpret_cast<float2*>(g_ctx + (size_t)(b*S + q0 + row0 + 8)*D + col) = o1;
        }
    }
}

extern "C" void kernel_launch(void* const* d_in, const int* in_sizes, int n_in,
                              void* d_out, int out_size) {
    (void)in_sizes; (void)n_in; (void)out_size;
    const float* query = (const float*)d_in[0];
    const float* key   = (const float*)d_in[1];
    const float* value = (const float*)d_in[2];
    const int*   mask  = (const int*)  d_in[3];
    const float* bias  = (const float*)d_in[4];
    const float* Wq    = (const float*)d_in[5];
    const float* Wk    = (const float*)d_in[6];
    const float* Wv    = (const float*)d_in[7];
    const float* Wo    = (const float*)d_in[8];

    float* out = (float*)d_out;                 // [B,S,D]
    float* om  = out + B*S*D;                   // [B,S,S] mean weights

    float *pctx;
    cudaGetSymbolAddress((void**)&pctx, g_ctx);

    cudaFuncSetAttribute(logits_mma, cudaFuncAttributeMaxDynamicSharedMemorySize, SMEM_LG);
    cudaFuncSetAttribute(pv_mma,     cudaFuncAttributeMaxDynamicSharedMemorySize, SMEM_PV);

    transpose_w<<<dim3(6,6,4), dim3(32,8)>>>(Wq, Wk, Wv, Wo);
    proj3_kernel<<<dim3(256,3), 128>>>(query, key, value);
    logits_mma<<<dim3(B*H, S/64), 256, SMEM_LG>>>(mask, bias);
    pv_mma<<<dim3(B, S/64), 256, SMEM_PV>>>(om);
    proj1_kernel<<<dim3(256,1), 128>>>(pctx, out);
}

// round 15
// speedup vs baseline: 1.0156x; 1.0156x over previous
#include <cuda_runtime.h>
#include <cuda_bf16.h>
#include <cstdint>

#define B 4
#define S 2048
#define H 4
#define DH 48
#define D 192
#define NEG_INF -1000000000.0f

// Scratch
__device__ float g_ctx[B*S*D];
__device__ float g_Linv[B*H*S];
__device__ float g_WT[4][D*D];                 // pre-transposed weights [k][j]
__device__ __nv_bfloat16 g_qh[B*H*S*DH];
__device__ __nv_bfloat16 g_ql[B*H*S*DH];
__device__ __nv_bfloat16 g_kh[B*H*S*DH];
__device__ __nv_bfloat16 g_kl[B*H*S*DH];
__device__ __nv_bfloat16 g_vh[B*H*S*DH];
__device__ __nv_bfloat16 g_vl[B*H*S*DH];
// E stored j-PERMUTED (fragment-native): within each 32-j group,
// actual a = 2p + 8t + u  <->  virtual v = 8p + 2t + u.
__device__ __nv_bfloat16 g_Eh[(size_t)B*H*S*S];
__device__ __nv_bfloat16 g_El[(size_t)B*H*S*S];

// ---------- packed fp32x2 helpers ----------
__device__ __forceinline__ unsigned long long pack2(float x, float y) {
    unsigned long long r;
    asm("mov.b64 %0, {%1,%2};" : "=l"(r) : "f"(x), "f"(y));
    return r;
}
__device__ __forceinline__ void unpack2(unsigned long long v, float& x, float& y) {
    asm("mov.b64 {%0,%1}, %2;" : "=f"(x), "=f"(y) : "l"(v));
}
__device__ __forceinline__ void ffma2(unsigned long long& d, unsigned long long a, unsigned long long b) {
    asm("fma.rn.f32x2 %0, %1, %2, %0;" : "+l"(d) : "l"(a), "l"(b));
}

// ---------- fast exp on the FMA pipe ----------
__device__ __forceinline__ float fexp(float x) {
    float y = fmaxf(x * 1.44269504f, -126.0f);
    float t = y + 12582912.0f;
    float f = y - (t - 12582912.0f);
    int   e = __float_as_int(t) - 0x4B400000;
    float s = __int_as_float((e + 127) << 23);
    float p =              1.3333558e-3f;
    p = fmaf(p, f, 9.6181291e-3f);
    p = fmaf(p, f, 5.5504109e-2f);
    p = fmaf(p, f, 2.4022651e-1f);
    p = fmaf(p, f, 6.9314718e-1f);
    p = fmaf(p, f, 1.0f);
    return p * s;
}

// packed bf16x2 convert: lo16 = cvt(a), hi16 = cvt(b)
__device__ __forceinline__ uint32_t cvt2bf(float a, float b) {
    uint32_t r;
    asm("cvt.rn.bf16x2.f32 %0, %1, %2;" : "=r"(r) : "f"(b), "f"(a));
    return r;
}

// ---------- cp.async helpers ----------
__device__ __forceinline__ void cp16(uint32_t saddr, const void* gptr) {
    asm volatile("cp.async.cg.shared.global [%0], [%1], 16;" :: "r"(saddr), "l"(gptr));
}
__device__ __forceinline__ void cp_commit() { asm volatile("cp.async.commit_group;"); }
__device__ __forceinline__ void cp_wait2()  { asm volatile("cp.async.wait_group 2;"); }
__device__ __forceinline__ void cp_wait1()  { asm volatile("cp.async.wait_group 1;"); }
__device__ __forceinline__ void cp_wait0()  { asm volatile("cp.async.wait_group 0;"); }
__device__ __forceinline__ uint32_t cvta_s(const void* p) {
    return (uint32_t)__cvta_generic_to_shared(p);
}
__device__ __forceinline__ void l2_prefetch(const void* p) {
    asm volatile("prefetch.global.L2 [%0];" :: "l"(p));
}

// ---------- mma.sync / ldmatrix helpers ----------
__device__ __forceinline__ void ldsm4(uint32_t addr, uint32_t* r) {
    asm volatile("ldmatrix.sync.aligned.m8n8.x4.shared.b16 {%0,%1,%2,%3}, [%4];"
                 : "=r"(r[0]), "=r"(r[1]), "=r"(r[2]), "=r"(r[3]) : "r"(addr));
}
__device__ __forceinline__ void ldsm4t(uint32_t addr, uint32_t* r) {
    asm volatile("ldmatrix.sync.aligned.m8n8.x4.trans.shared.b16 {%0,%1,%2,%3}, [%4];"
                 : "=r"(r[0]), "=r"(r[1]), "=r"(r[2]), "=r"(r[3]) : "r"(addr));
}
__device__ __forceinline__ void ldsm2t(uint32_t addr, uint32_t* r) {
    asm volatile("ldmatrix.sync.aligned.m8n8.x2.trans.shared.b16 {%0,%1}, [%2];"
                 : "=r"(r[0]), "=r"(r[1]) : "r"(addr));
}
__device__ __forceinline__ void mma16816(float* c, const uint32_t* a, const uint32_t* b) {
    asm volatile("mma.sync.aligned.m16n8k16.row.col.f32.bf16.bf16.f32 "
                 "{%0,%1,%2,%3}, {%4,%5,%6,%7}, {%8,%9}, {%0,%1,%2,%3};"
                 : "+f"(c[0]), "+f"(c[1]), "+f"(c[2]), "+f"(c[3])
                 : "r"(a[0]), "r"(a[1]), "r"(a[2]), "r"(a[3]), "r"(b[0]), "r"(b[1]));
}

// ---------- weight transpose ----------
__global__ void transpose_w(const float* __restrict__ W0, const float* __restrict__ W1,
                            const float* __restrict__ W2, const float* __restrict__ W3) {
    __shared__ float tile[32][33];
    const float* W = (blockIdx.z == 0) ? W0 : (blockIdx.z == 1) ? W1 : (blockIdx.z == 2) ? W2 : W3;
    float* WT = g_WT[blockIdx.z];
    int x = blockIdx.x*32 + threadIdx.x;
    int y = blockIdx.y*32 + threadIdx.y;
    #pragma unroll
    for (int j = 0; j < 32; j += 8)
        tile[threadIdx.y + j][threadIdx.x] = W[(y + j)*D + x];
    __syncthreads();
    int x2 = blockIdx.y*32 + threadIdx.x;
    int y2 = blockIdx.x*32 + threadIdx.y;
    #pragma unroll
    for (int j = 0; j < 32; j += 8)
        WT[(y2 + j)*D + x2] = tile[threadIdx.x][threadIdx.y + j];
}

// ---------- projection core ----------
template<bool BF16OUT>
__device__ __forceinline__ void proj_core(const float* __restrict__ X,
                                          const float* __restrict__ WT,
                                          float* __restrict__ Yf,
                                          __nv_bfloat16* __restrict__ Yh,
                                          __nv_bfloat16* __restrict__ Yl,
                                          int r0) {
    __shared__ float sXT[192*33];
    const int tid = threadIdx.x;
    const int w = tid >> 5, lane = tid & 31;

    #pragma unroll
    for (int k = 0; k < 12; k++) {
        int idx = tid + k*128;
        int r = idx / 48, c = idx % 48;
        float4 v = *reinterpret_cast<const float4*>(X + (size_t)(r0 + r)*D + 4*c);
        sXT[(4*c+0)*33 + r] = v.x;
        sXT[(4*c+1)*33 + r] = v.y;
        sXT[(4*c+2)*33 + r] = v.z;
        sXT[(4*c+3)*33 + r] = v.w;
    }
    __syncthreads();

    unsigned long long acc[8][3];
    #pragma unroll
    for (int i = 0; i < 8; i++)
        #pragma unroll
        for (int p = 0; p < 3; p++) acc[i][p] = 0ull;

    #pragma unroll 2
    for (int k = 0; k < 192; k++) {
        const unsigned long long* wrow =
            reinterpret_cast<const unsigned long long*>(WT + k*D + lane*6);
        unsigned long long w0 = wrow[0], w1 = wrow[1], w2 = wrow[2];
        #pragma unroll
        for (int i = 0; i < 8; i++) {
            float xv = sXT[k*33 + w*8 + i];
            unsigned long long x2 = pack2(xv, xv);
            ffma2(acc[i][0], x2, w0);
            ffma2(acc[i][1], x2, w1);
            ffma2(acc[i][2], x2, w2);
        }
    }
    #pragma unroll
    for (int i = 0; i < 8; i++) {
        const int row = r0 + w*8 + i;      // b*S + s
        if (BF16OUT) {
            const int bb = row >> 11, s = row & 2047;
            const int hh = lane >> 3, c0 = (lane & 7)*6;
            size_t base = ((size_t)(bb*H + hh)*S + s)*DH + c0;
            #pragma unroll
            for (int m = 0; m < 3; m++) {
                float x, y; unpack2(acc[i][m], x, y);
                __nv_bfloat16 hx = __float2bfloat16(x);
                __nv_bfloat16 hy = __float2bfloat16(y);
                float lx = x - __bfloat162float(hx);
                float ly = y - __bfloat162float(hy);
                __nv_bfloat162 hv; hv.x = hx; hv.y = hy;
                __nv_bfloat162 lv; lv.x = __float2bfloat16(lx); lv.y = __float2bfloat16(ly);
                *reinterpret_cast<__nv_bfloat162*>(Yh + base + 2*m) = hv;
                *reinterpret_cast<__nv_bfloat162*>(Yl + base + 2*m) = lv;
            }
        } else {
            unsigned long long* dst =
                reinterpret_cast<unsigned long long*>(Yf + (size_t)row*D + lane*6);
            dst[0] = acc[i][0]; dst[1] = acc[i][1]; dst[2] = acc[i][2];
        }
    }
}

__global__ __launch_bounds__(128, 4) void proj3_kernel(const float* __restrict__ Xq,
                                                       const float* __restrict__ Xk,
                                                       const float* __restrict__ Xv) {
    const int which = blockIdx.y;
    const int r0 = blockIdx.x * 32;
    if (which == 2)      proj_core<true >(Xv, g_WT[2], nullptr, g_vh, g_vl, r0);
    else if (which == 0) proj_core<true >(Xq, g_WT[0], nullptr, g_qh, g_ql, r0);
    else                 proj_core<true >(Xk, g_WT[1], nullptr, g_kh, g_kl, r0);
}

__global__ __launch_bounds__(128, 4) void proj1_kernel(const float* __restrict__ X,
                                                       float* __restrict__ Y) {
    proj_core<false>(X, g_WT[3], Y, nullptr, nullptr, blockIdx.x * 32);
}

// ============================================================================
// logits_mma: b-major grid, int32 mask, packed permuted E stores (wb).
// NEW: L2 prefetch of next tile's mask+bias during the MMA phase, and packed
// bf16x2 converts (shift/mask hi-extraction) in the epilogue.
// ============================================================================
#define OFF_QH 0
#define OFF_QL 8192
#define OFF_KH 16384
#define OFF_KL 49152
#define OFF_SUM 81920
#define SMEM_LG (OFF_SUM + 64*4*4)

__global__ __launch_bounds__(256, 2) void logits_mma(const int* __restrict__ gmask,
                                                     const float* __restrict__ gbias) {
    extern __shared__ char smem[];
    const uint32_t sb = cvta_s(smem);
    float (*sums)[4] = reinterpret_cast<float(*)[4]>(smem + OFF_SUM);
    const int tid = threadIdx.x;
    const int warp = tid >> 5, lane = tid & 31;
    const int bh = blockIdx.x;
    const int b  = bh >> 2, h = bh & 3;
    const int q0 = blockIdx.y * 64;
    const int qw = (warp >> 2) * 32;
    const int jw = (warp & 3) * 32;

    {
        const __nv_bfloat16* qh = g_qh + ((size_t)bh*S + q0)*DH;
        const __nv_bfloat16* ql = g_ql + ((size_t)bh*S + q0)*DH;
        #pragma unroll
        for (int k = 0; k < 2; k++) {
            int idx = tid + k*256;
            if (idx < 384) {
                int r = idx / 6, c = idx % 6;
                uint32_t off = r*128 + ((c ^ (r&7))<<4);
                cp16(sb + OFF_QH + off, qh + r*DH + c*8);
                cp16(sb + OFF_QL + off, ql + r*DH + c*8);
            }
        }
        const __nv_bfloat16* kh = g_kh + (size_t)bh*S*DH;
        const __nv_bfloat16* kl = g_kl + (size_t)bh*S*DH;
        #pragma unroll
        for (int k = 0; k < 3; k++) {
            int idx = tid + k*256;
            int r = idx / 6, c = idx % 6;
            uint32_t off = r*128 + ((c ^ (r&7))<<4);
            cp16(sb + OFF_KH + off, kh + r*DH + c*8);
            cp16(sb + OFF_KL + off, kl + r*DH + c*8);
        }
        cp_commit();
    }
    // prefetch tile 0's mask/bias lines into L2 (one 128B line per thread each)
    {
        const int prow = tid >> 2, pcol = (tid & 3) * 32;
        l2_prefetch(gmask + (size_t)(b*S + q0 + prow)*S + pcol);
        l2_prefetch(gbias + (size_t)(h*S + q0 + prow)*S + pcol);
    }
    cp_wait0();
    __syncthreads();

    uint32_t ah[2][3][4];
    #pragma unroll
    for (int mi = 0; mi < 2; mi++)
        #pragma unroll
        for (int ks = 0; ks < 3; ks++) {
            int r = qw + mi*16 + (lane & 7) + ((lane >> 3) & 1)*8;
            int c = ks*2 + (lane >> 4);
            ldsm4(sb + OFF_QH + r*128 + ((c ^ (r&7))<<4), ah[mi][ks]);
        }

    float lsum[4] = {0.f, 0.f, 0.f, 0.f};

    for (int jt = 0; jt < 16; jt++) {
        const uint32_t kbH = sb + OFF_KH + (jt & 1)*16384;
        const uint32_t kbL = sb + OFF_KL + (jt & 1)*16384;

        if (jt + 1 < 16) {
            const uint32_t nH = sb + OFF_KH + ((jt+1) & 1)*16384;
            const uint32_t nL = sb + OFF_KL + ((jt+1) & 1)*16384;
            const __nv_bfloat16* kh = g_kh + ((size_t)bh*S + (jt+1)*128)*DH;
            const __nv_bfloat16* kl = g_kl + ((size_t)bh*S + (jt+1)*128)*DH;
            #pragma unroll
            for (int k = 0; k < 3; k++) {
                int idx = tid + k*256;
                int r = idx / 6, c = idx % 6;
                uint32_t off = r*128 + ((c ^ (r&7))<<4);
                cp16(nH + off, kh + r*DH + c*8);
                cp16(nL + off, kl + r*DH + c*8);
            }
            cp_commit();
            // prefetch next tile's mask/bias into L2 (overlaps MMA below)
            const int prow = tid >> 2, pcol = (tid & 3) * 32;
            l2_prefetch(gmask + (size_t)(b*S + q0 + prow)*S + (jt+1)*128 + pcol);
            l2_prefetch(gbias + (size_t)(h*S + q0 + prow)*S + (jt+1)*128 + pcol);
        }

        float acc[2][4][4];
        #pragma unroll
        for (int mi = 0; mi < 2; mi++)
            #pragma unroll
            for (int nj = 0; nj < 4; nj++)
                #pragma unroll
                for (int p = 0; p < 4; p++) acc[mi][nj][p] = 0.f;

        #pragma unroll
        for (int ks = 0; ks < 3; ks++) {
            uint32_t bhf[2][4], blf[2][4], alf[2][4];
            #pragma unroll
            for (int jj = 0; jj < 2; jj++) {
                int r = jw + jj*16 + (lane & 7) + (lane >> 4)*8;
                int c = ks*2 + ((lane >> 3) & 1);
                uint32_t off = r*128 + ((c ^ (r&7))<<4);
                ldsm4(kbH + off, bhf[jj]);
                ldsm4(kbL + off, blf[jj]);
            }
            #pragma unroll
            for (int mi = 0; mi < 2; mi++) {
                int r = qw + mi*16 + (lane & 7) + ((lane >> 3) & 1)*8;
                int c = ks*2 + (lane >> 4);
                ldsm4(sb + OFF_QL + r*128 + ((c ^ (r&7))<<4), alf[mi]);
            }
            #pragma unroll
            for (int mi = 0; mi < 2; mi++)
                #pragma unroll
                for (int jj = 0; jj < 2; jj++)
                    #pragma unroll
                    for (int sub = 0; sub < 2; sub++) {
                        float* a = acc[mi][jj*2 + sub];
                        mma16816(a, ah[mi][ks], &bhf[jj][sub*2]);
                        mma16816(a, ah[mi][ks], &blf[jj][sub*2]);
                        mma16816(a, alf[mi],    &bhf[jj][sub*2]);
                    }
        }
        __syncthreads();

        const int jbase  = jt*128 + jw + (lane & 3)*2;   // actual j base
        const int jvbase = jt*128 + jw + 8*(lane & 3);   // virtual (permuted)
        #pragma unroll
        for (int mi = 0; mi < 2; mi++)
            #pragma unroll
            for (int h2 = 0; h2 < 2; h2++) {
                const int qrow = q0 + qw + mi*16 + h2*8 + (lane >> 2);
                const int*   mrow = gmask + (size_t)(b*S + qrow)*S + jbase;
                const float* brow = gbias + (size_t)(h*S + qrow)*S + jbase;
                float ls = 0.f;
                uint32_t hw[4], lw[4];
                #pragma unroll
                for (int nj = 0; nj < 4; nj++) {
                    int2   mv = *reinterpret_cast<const int2*>(mrow + nj*8);
                    float2 bv = *reinterpret_cast<const float2*>(brow + nj*8);
                    float e0 = fexp(mv.x ? acc[mi][nj][h2*2+0] + bv.x : NEG_INF);
                    float e1 = fexp(mv.y ? acc[mi][nj][h2*2+1] + bv.y : NEG_INF);
                    uint32_t hp = cvt2bf(e0, e1);
                    float h0 = __uint_as_float(hp << 16);
                    float h1 = __uint_as_float(hp & 0xFFFF0000u);
                    uint32_t lp = cvt2bf(e0 - h0, e1 - h1);
                    hw[nj] = hp;
                    lw[nj] = lp;
                    ls += e0 + e1;
                }
                uint4 hq; hq.x = hw[0]; hq.y = hw[1]; hq.z = hw[2]; hq.w = hw[3];
                uint4 lq; lq.x = lw[0]; lq.y = lw[1]; lq.z = lw[2]; lq.w = lw[3];
                *reinterpret_cast<uint4*>(g_Eh + ((size_t)bh*S + qrow)*S + jvbase) = hq;
                *reinterpret_cast<uint4*>(g_El + ((size_t)bh*S + qrow)*S + jvbase) = lq;
                lsum[mi*2 + h2] += ls;
            }

        cp_wait0();
    }

    #pragma unroll
    for (int k = 0; k < 4; k++) {
        float v = lsum[k];
        v += __shfl_xor_sync(0xffffffffu, v, 1);
        v += __shfl_xor_sync(0xffffffffu, v, 2);
        if ((lane & 3) == 0)
            sums[qw + (k >> 1)*16 + (k & 1)*8 + (lane >> 2)][warp & 3] = v;
    }
    __syncthreads();
    if (tid < 64) {
        float L = sums[tid][0] + sums[tid][1] + sums[tid][2] + sums[tid][3];
        g_Linv[(size_t)bh*S + q0 + tid] = 1.0f / L;
    }
}

// ============================================================================
// pv_mma: DEPTH-3 cp.async pipeline (R14 version, best measured: 134.2us)
// ============================================================================
#define PM_OFF_LINV 33792
#define PM_OFF_TILE 34816
#define PM_BUF 65536
#define PM_EH 0
#define PM_EL 16384
#define PM_VH 32768
#define PM_VL 49152
#define SMEM_PV (PM_OFF_TILE + 3*PM_BUF)   // 231424 B = 226 KB

__global__ __launch_bounds__(256, 1) void pv_mma(float* __restrict__ om) {
    extern __shared__ char smem[];
    const uint32_t sb = cvta_s(smem);
    float* sMean  = reinterpret_cast<float*>(smem);                 // [64][132]
    float* sLinvf = reinterpret_cast<float*>(smem + PM_OFF_LINV);   // [4][64]
    const int tid = threadIdx.x;
    const int warp = tid >> 5, lane = tid & 31;
    const int b  = blockIdx.x;
    const int q0 = blockIdx.y * 64;
    const int q0w = (warp >> 1) * 16;
    const int wd  = warp & 1;
    const int cV  = wd * 3;

    {
        int hh = tid >> 6, q = tid & 63;
        sLinvf[tid] = g_Linv[(size_t)(b*H + hh)*S + q0 + q];
    }

    auto load_stage = [&](int st, uint32_t bufb) {
        const int jt = st >> 2, hh = st & 3;
        const int bhl = b*H + hh;
        const __nv_bfloat16* ehp = g_Eh + ((size_t)bhl*S + q0)*S + jt*128;
        const __nv_bfloat16* elp = g_El + ((size_t)bhl*S + q0)*S + jt*128;
        #pragma unroll
        for (int k = 0; k < 4; k++) {
            int idx = tid + k*256;
            int r = idx >> 4, cj = idx & 15;
            uint32_t off = r*256 + ((cj ^ (r&7))<<4);
            cp16(bufb + PM_EH + off, ehp + (size_t)r*S + cj*8);
            cp16(bufb + PM_EL + off, elp + (size_t)r*S + cj*8);
        }
        const __nv_bfloat16* vhp = g_vh + ((size_t)bhl*S + jt*128)*DH;
        const __nv_bfloat16* vlp = g_vl + ((size_t)bhl*S + jt*128)*DH;
        #pragma unroll
        for (int k = 0; k < 3; k++) {
            int idx = tid + k*256;
            int r = idx / 6, c = idx % 6;
            int vr = (r & 96) | (8*((r&7)>>1) + 2*((r>>3)&3) + (r&1));
            uint32_t off = vr*128 + ((c ^ (vr&7))<<4);
            cp16(bufb + PM_VH + off, vhp + r*DH + c*8);
            cp16(bufb + PM_VL + off, vlp + r*DH + c*8);
        }
    };

    load_stage(0, sb + PM_OFF_TILE + 0*PM_BUF);
    cp_commit();
    load_stage(1, sb + PM_OFF_TILE + 1*PM_BUF);
    cp_commit();
    __syncthreads();

    float acc[4][3][4];
    #pragma unroll
    for (int hh = 0; hh < 4; hh++)
        #pragma unroll
        for (int nt = 0; nt < 3; nt++)
            #pragma unroll
            for (int p = 0; p < 4; p++) acc[hh][nt][p] = 0.f;

    for (int jt = 0; jt < 16; jt++) {
        #pragma unroll
        for (int hh = 0; hh < 4; hh++) {
            const int st = jt*4 + hh;
            if (st + 2 < 64) {
                load_stage(st + 2, sb + PM_OFF_TILE + ((st+2) % 3)*PM_BUF);
                cp_commit();
                cp_wait2();
            } else {
                cp_wait0();
            }
            __syncthreads();
            const uint32_t tb = sb + PM_OFF_TILE + (st % 3)*PM_BUF;
            const char*   tbp = smem + PM_OFF_TILE + (st % 3)*PM_BUF;

            #pragma unroll
            for (int k = 0; k < 4; k++) {
                int idx = tid + k*256;
                int q = idx >> 4, cj = idx & 15;
                uint32_t eoff = q*256 + ((cj ^ (q&7))<<4);
                uint4 uh = *reinterpret_cast<const uint4*>(tbp + PM_EH + eoff);
                uint4 ul = *reinterpret_cast<const uint4*>(tbp + PM_EL + eoff);
                float linv = sLinvf[hh*64 + q];
                float2 f0 = __bfloat1622float2(*reinterpret_cast<__nv_bfloat162*>(&uh.x));
                float2 f1 = __bfloat1622float2(*reinterpret_cast<__nv_bfloat162*>(&uh.y));
                float2 f2 = __bfloat1622float2(*reinterpret_cast<__nv_bfloat162*>(&uh.z));
                float2 f3 = __bfloat1622float2(*reinterpret_cast<__nv_bfloat162*>(&uh.w));
                float2 g0 = __bfloat1622float2(*reinterpret_cast<__nv_bfloat162*>(&ul.x));
                float2 g1 = __bfloat1622float2(*reinterpret_cast<__nv_bfloat162*>(&ul.y));
                float2 g2 = __bfloat1622float2(*reinterpret_cast<__nv_bfloat162*>(&ul.z));
                float2 g3 = __bfloat1622float2(*reinterpret_cast<__nv_bfloat162*>(&ul.w));
                float* mp = sMean + q*132 + cj*8;
                if (hh == 0) {
                    float4 m0, m1;
                    m0.x = (f0.x+g0.x)*linv; m0.y = (f0.y+g0.y)*linv;
                    m0.z = (f1.x+g1.x)*linv; m0.w = (f1.y+g1.y)*linv;
                    m1.x = (f2.x+g2.x)*linv; m1.y = (f2.y+g2.y)*linv;
                    m1.z = (f3.x+g3.x)*linv; m1.w = (f3.y+g3.y)*linv;
                    *reinterpret_cast<float4*>(mp)     = m0;
                    *reinterpret_cast<float4*>(mp + 4) = m1;
                } else {
                    float4 m0 = *reinterpret_cast<float4*>(mp);
                    float4 m1 = *reinterpret_cast<float4*>(mp + 4);
                    m0.x += (f0.x+g0.x)*linv; m0.y += (f0.y+g0.y)*linv;
                    m0.z += (f1.x+g1.x)*linv; m0.w += (f1.y+g1.y)*linv;
                    m1.x += (f2.x+g2.x)*linv; m1.y += (f2.y+g2.y)*linv;
                    m1.z += (f3.x+g3.x)*linv; m1.w += (f3.y+g3.y)*linv;
                    *reinterpret_cast<float4*>(mp)     = m0;
                    *reinterpret_cast<float4*>(mp + 4) = m1;
                }
            }

            #pragma unroll
            for (int ks = 0; ks < 8; ks++) {
                int ra = q0w + (lane & 15);
                int ca = ks*2 + (lane >> 4);
                uint32_t aoff = ra*256 + ((ca ^ (ra&7))<<4);
                uint32_t ahf[4], alf[4];
                ldsm4(tb + PM_EH + aoff, ahf);
                ldsm4(tb + PM_EL + aoff, alf);

                int rb = ks*16 + (lane & 15);
                int cb4 = cV + (lane >> 4);
                uint32_t boff4 = rb*128 + ((cb4 ^ (rb&7))<<4);
                uint32_t bh4[4], bl4[4];
                ldsm4t(tb + PM_VH + boff4, bh4);
                ldsm4t(tb + PM_VL + boff4, bl4);
                int cb2 = cV + 2;
                uint32_t boff2 = rb*128 + ((cb2 ^ (rb&7))<<4);
                uint32_t bh2[2], bl2[2];
                ldsm2t(tb + PM_VH + boff2, bh2);
                ldsm2t(tb + PM_VL + boff2, bl2);

                #pragma unroll
                for (int nt = 0; nt < 2; nt++) {
                    float* a = acc[hh][nt];
                    mma16816(a, ahf, &bh4[nt*2]);
                    mma16816(a, ahf, &bl4[nt*2]);
                    mma16816(a, alf, &bh4[nt*2]);
                }
                {
                    float* a = acc[hh][2];
                    mma16816(a, ahf, bh2);
                    mma16816(a, ahf, bl2);
                    mma16816(a, alf, bh2);
                }
            }

            if (hh == 3) {
                __syncthreads();
                #pragma unroll
                for (int k = 0; k < 8; k++) {
                    int idx = tid + k*256;
                    int q = idx >> 5, c4 = idx & 31;
                    int g = (c4 >> 3) << 5;
                    int r32 = (4*c4) & 31;
                    int v0 = g + 8*((r32 & 7) >> 1) + 2*(r32 >> 3);
                    float2 m0 = *reinterpret_cast<const float2*>(sMean + q*132 + v0);
                    float2 m1 = *reinterpret_cast<const float2*>(sMean + q*132 + v0 + 8);
                    float4 r;
                    r.x = 0.25f*m0.x; r.y = 0.25f*m0.y;
                    r.z = 0.25f*m1.x; r.w = 0.25f*m1.y;
                    *reinterpret_cast<float4*>(om + (size_t)(b*S + q0 + q)*S + jt*128 + c4*4) = r;
                }
            }
            __syncthreads();
        }
    }

    #pragma unroll
    for (int hh = 0; hh < 4; hh++) {
        const int row0 = q0w + (lane >> 2);
        const float l0 = sLinvf[hh*64 + row0];
        const float l1 = sLinvf[hh*64 + row0 + 8];
        #pragma unroll
        for (int nt = 0; nt < 3; nt++) {
            const int col = hh*48 + wd*24 + nt*8 + (lane & 3)*2;
            float2 o0; o0.x = acc[hh][nt][0]*l0; o0.y = acc[hh][nt][1]*l0;
            float2 o1; o1.x = acc[hh][nt][2]*l1; o1.y = acc[hh][nt][3]*l1;
            *reinterpret_cast<float2*>(g_ctx + (size_t)(b*S + q0 + row0)*D + col)     = o0;
            *reinterpret_cast<float2*>(g_ctx + (size_t)(b*S + q0 + row0 + 8)*D + col) = o1;
        }
    }
}

extern "C" void kernel_launch(void* const* d_in, const int* in_sizes, int n_in,
                              void* d_out, int out_size) {
    (void)in_sizes; (void)n_in; (void)out_size;
    const float* query = (const float*)d_in[0];
    const float* key   = (const float*)d_in[1];
    const float* value = (const float*)d_in[2];
    const int*   mask  = (const int*)  d_in[3];
    const float* bias  = (const float*)d_in[4];
    const float* Wq    = (const float*)d_in[5];
    const float* Wk    = (const float*)d_in[6];
    const float* Wv    = (const float*)d_in[7];
    const float* Wo    = (const float*)d_in[8];

    float* out = (float*)d_out;                 // [B,S,D]
    float* om  = out + B*S*D;                   // [B,S,S] mean weights

    float *pctx;
    cudaGetSymbolAddress((void**)&pctx, g_ctx);

    cudaFuncSetAttribute(logits_mma, cudaFuncAttributeMaxDynamicSharedMemorySize, SMEM_LG);
    cudaFuncSetAttribute(pv_mma,     cudaFuncAttributeMaxDynamicSharedMemorySize, SMEM_PV);

    transpose_w<<<dim3(6,6,4), dim3(32,8)>>>(Wq, Wk, Wv, Wo);
    proj3_kernel<<<dim3(256,3), 128>>>(query, key, value);
    logits_mma<<<dim3(B*H, S/64), 256, SMEM_LG>>>(mask, bias);
    pv_mma<<<dim3(B, S/64), 256, SMEM_PV>>>(om);
    proj1_kernel<<<dim3(256,1), 128>>>(pctx, out);
}

// round 16
// speedup vs baseline: 1.1401x; 1.1226x over previous
#include <cuda_runtime.h>
#include <cuda_bf16.h>
#include <cstdint>

#define B 4
#define S 2048
#define H 4
#define DH 48
#define D 192
#define NEG_INF -1000000000.0f

// Scratch
__device__ float g_ctx[B*S*D];
__device__ float g_Linv[B*H*S];
__device__ float g_WT[4][D*D];
__device__ uint32_t g_mbits[B*S*64];           // bit-packed mask (2MB)
__device__ __nv_bfloat16 g_qh[B*H*S*DH];
__device__ __nv_bfloat16 g_ql[B*H*S*DH];
__device__ __nv_bfloat16 g_kh[B*H*S*DH];
__device__ __nv_bfloat16 g_kl[B*H*S*DH];
__device__ __nv_bfloat16 g_vh[B*H*S*DH];
__device__ __nv_bfloat16 g_vl[B*H*S*DH];
// E stored j-PERMUTED (fragment-native): within each 32-j group,
// actual a = 2p + 8t + u  <->  virtual v = 8p + 2t + u.
__device__ __nv_bfloat16 g_Eh[(size_t)B*H*S*S];
__device__ __nv_bfloat16 g_El[(size_t)B*H*S*S];

// ---------- packed fp32x2 helpers ----------
__device__ __forceinline__ unsigned long long pack2(float x, float y) {
    unsigned long long r;
    asm("mov.b64 %0, {%1,%2};" : "=l"(r) : "f"(x), "f"(y));
    return r;
}
__device__ __forceinline__ void unpack2(unsigned long long v, float& x, float& y) {
    asm("mov.b64 {%0,%1}, %2;" : "=f"(x), "=f"(y) : "l"(v));
}
__device__ __forceinline__ void ffma2(unsigned long long& d, unsigned long long a, unsigned long long b) {
    asm("fma.rn.f32x2 %0, %1, %2, %0;" : "+l"(d) : "l"(a), "l"(b));
}

// ---------- fast exp on the FMA pipe ----------
__device__ __forceinline__ float fexp(float x) {
    float y = fmaxf(x * 1.44269504f, -126.0f);
    float t = y + 12582912.0f;
    float f = y - (t - 12582912.0f);
    int   e = __float_as_int(t) - 0x4B400000;
    float s = __int_as_float((e + 127) << 23);
    float p =              1.3333558e-3f;
    p = fmaf(p, f, 9.6181291e-3f);
    p = fmaf(p, f, 5.5504109e-2f);
    p = fmaf(p, f, 2.4022651e-1f);
    p = fmaf(p, f, 6.9314718e-1f);
    p = fmaf(p, f, 1.0f);
    return p * s;
}

// packed bf16x2 convert: lo16 = cvt(a), hi16 = cvt(b)
__device__ __forceinline__ uint32_t cvt2bf(float a, float b) {
    uint32_t r;
    asm("cvt.rn.bf16x2.f32 %0, %1, %2;" : "=r"(r) : "f"(b), "f"(a));
    return r;
}

// ---------- cp.async helpers ----------
__device__ __forceinline__ void cp16(uint32_t saddr, const void* gptr) {
    asm volatile("cp.async.cg.shared.global [%0], [%1], 16;" :: "r"(saddr), "l"(gptr));
}
__device__ __forceinline__ void cp_commit() { asm volatile("cp.async.commit_group;"); }
__device__ __forceinline__ void cp_wait2()  { asm volatile("cp.async.wait_group 2;"); }
__device__ __forceinline__ void cp_wait1()  { asm volatile("cp.async.wait_group 1;"); }
__device__ __forceinline__ void cp_wait0()  { asm volatile("cp.async.wait_group 0;"); }
__device__ __forceinline__ uint32_t cvta_s(const void* p) {
    return (uint32_t)__cvta_generic_to_shared(p);
}

// ---------- mma.sync / ldmatrix helpers ----------
__device__ __forceinline__ void ldsm4(uint32_t addr, uint32_t* r) {
    asm volatile("ldmatrix.sync.aligned.m8n8.x4.shared.b16 {%0,%1,%2,%3}, [%4];"
                 : "=r"(r[0]), "=r"(r[1]), "=r"(r[2]), "=r"(r[3]) : "r"(addr));
}
__device__ __forceinline__ void ldsm4t(uint32_t addr, uint32_t* r) {
    asm volatile("ldmatrix.sync.aligned.m8n8.x4.trans.shared.b16 {%0,%1,%2,%3}, [%4];"
                 : "=r"(r[0]), "=r"(r[1]), "=r"(r[2]), "=r"(r[3]) : "r"(addr));
}
__device__ __forceinline__ void ldsm2t(uint32_t addr, uint32_t* r) {
    asm volatile("ldmatrix.sync.aligned.m8n8.x2.trans.shared.b16 {%0,%1}, [%2];"
                 : "=r"(r[0]), "=r"(r[1]) : "r"(addr));
}
__device__ __forceinline__ void mma16816(float* c, const uint32_t* a, const uint32_t* b) {
    asm volatile("mma.sync.aligned.m16n8k16.row.col.f32.bf16.bf16.f32 "
                 "{%0,%1,%2,%3}, {%4,%5,%6,%7}, {%8,%9}, {%0,%1,%2,%3};"
                 : "+f"(c[0]), "+f"(c[1]), "+f"(c[2]), "+f"(c[3])
                 : "r"(a[0]), "r"(a[1]), "r"(a[2]), "r"(a[3]), "r"(b[0]), "r"(b[1]));
}

// ---------- mask -> bit pack ----------
__global__ __launch_bounds__(256) void mbits_kernel(const int* __restrict__ m) {
    const int row = blockIdx.x*8 + (threadIdx.x >> 5);
    const int lane = threadIdx.x & 31;
    const int* mr = m + (size_t)row * S;
    uint32_t w0 = 0, w1 = 0;
    #pragma unroll 4
    for (int it = 0; it < 64; it++) {
        uint32_t bal = __ballot_sync(0xffffffffu, mr[it*32 + lane] != 0);
        if ((it & 31) == lane) { if (it < 32) w0 = bal; else w1 = bal; }
    }
    g_mbits[(size_t)row*64 + lane]      = w0;
    g_mbits[(size_t)row*64 + 32 + lane] = w1;
}

// ---------- weight transpose ----------
__global__ void transpose_w(const float* __restrict__ W0, const float* __restrict__ W1,
                            const float* __restrict__ W2, const float* __restrict__ W3) {
    __shared__ float tile[32][33];
    const float* W = (blockIdx.z == 0) ? W0 : (blockIdx.z == 1) ? W1 : (blockIdx.z == 2) ? W2 : W3;
    float* WT = g_WT[blockIdx.z];
    int x = blockIdx.x*32 + threadIdx.x;
    int y = blockIdx.y*32 + threadIdx.y;
    #pragma unroll
    for (int j = 0; j < 32; j += 8)
        tile[threadIdx.y + j][threadIdx.x] = W[(y + j)*D + x];
    __syncthreads();
    int x2 = blockIdx.y*32 + threadIdx.x;
    int y2 = blockIdx.x*32 + threadIdx.y;
    #pragma unroll
    for (int j = 0; j < 32; j += 8)
        WT[(y2 + j)*D + x2] = tile[threadIdx.x][threadIdx.y + j];
}

// ---------- projection core ----------
template<bool BF16OUT>
__device__ __forceinline__ void proj_core(const float* __restrict__ X,
                                          const float* __restrict__ WT,
                                          float* __restrict__ Yf,
                                          __nv_bfloat16* __restrict__ Yh,
                                          __nv_bfloat16* __restrict__ Yl,
                                          int r0) {
    __shared__ float sXT[192*33];
    const int tid = threadIdx.x;
    const int w = tid >> 5, lane = tid & 31;

    #pragma unroll
    for (int k = 0; k < 12; k++) {
        int idx = tid + k*128;
        int r = idx / 48, c = idx % 48;
        float4 v = *reinterpret_cast<const float4*>(X + (size_t)(r0 + r)*D + 4*c);
        sXT[(4*c+0)*33 + r] = v.x;
        sXT[(4*c+1)*33 + r] = v.y;
        sXT[(4*c+2)*33 + r] = v.z;
        sXT[(4*c+3)*33 + r] = v.w;
    }
    __syncthreads();

    unsigned long long acc[8][3];
    #pragma unroll
    for (int i = 0; i < 8; i++)
        #pragma unroll
        for (int p = 0; p < 3; p++) acc[i][p] = 0ull;

    #pragma unroll 2
    for (int k = 0; k < 192; k++) {
        const unsigned long long* wrow =
            reinterpret_cast<const unsigned long long*>(WT + k*D + lane*6);
        unsigned long long w0 = wrow[0], w1 = wrow[1], w2 = wrow[2];
        #pragma unroll
        for (int i = 0; i < 8; i++) {
            float xv = sXT[k*33 + w*8 + i];
            unsigned long long x2 = pack2(xv, xv);
            ffma2(acc[i][0], x2, w0);
            ffma2(acc[i][1], x2, w1);
            ffma2(acc[i][2], x2, w2);
        }
    }
    #pragma unroll
    for (int i = 0; i < 8; i++) {
        const int row = r0 + w*8 + i;
        if (BF16OUT) {
            const int bb = row >> 11, s = row & 2047;
            const int hh = lane >> 3, c0 = (lane & 7)*6;
            size_t base = ((size_t)(bb*H + hh)*S + s)*DH + c0;
            #pragma unroll
            for (int m = 0; m < 3; m++) {
                float x, y; unpack2(acc[i][m], x, y);
                __nv_bfloat16 hx = __float2bfloat16(x);
                __nv_bfloat16 hy = __float2bfloat16(y);
                float lx = x - __bfloat162float(hx);
                float ly = y - __bfloat162float(hy);
                __nv_bfloat162 hv; hv.x = hx; hv.y = hy;
                __nv_bfloat162 lv; lv.x = __float2bfloat16(lx); lv.y = __float2bfloat16(ly);
                *reinterpret_cast<__nv_bfloat162*>(Yh + base + 2*m) = hv;
                *reinterpret_cast<__nv_bfloat162*>(Yl + base + 2*m) = lv;
            }
        } else {
            unsigned long long* dst =
                reinterpret_cast<unsigned long long*>(Yf + (size_t)row*D + lane*6);
            dst[0] = acc[i][0]; dst[1] = acc[i][1]; dst[2] = acc[i][2];
        }
    }
}

__global__ __launch_bounds__(128, 4) void proj3_kernel(const float* __restrict__ Xq,
                                                       const float* __restrict__ Xk,
                                                       const float* __restrict__ Xv) {
    const int which = blockIdx.y;
    const int r0 = blockIdx.x * 32;
    if (which == 2)      proj_core<true >(Xv, g_WT[2], nullptr, g_vh, g_vl, r0);
    else if (which == 0) proj_core<true >(Xq, g_WT[0], nullptr, g_qh, g_ql, r0);
    else                 proj_core<true >(Xk, g_WT[1], nullptr, g_kh, g_kl, r0);
}

__global__ __launch_bounds__(128, 4) void proj1_kernel(const float* __restrict__ X,
                                                       float* __restrict__ Y) {
    proj_core<false>(X, g_WT[3], Y, nullptr, nullptr, blockIdx.x * 32);
}

// ============================================================================
// logits_mma: epilogue inputs fully smem-staged.
//  - bias tile [64][136] f32 (conflict-free, 16B-aligned rows) cp.async'd one
//    tile ahead, single buffer aliased over the dead QH region + sums.
//  - mask staged as bit-words (1KB/tile).
// Group schedule per iter: commit K(jt+1); wait2 (K(jt) landed); MMA; wait1
// (bias(jt) landed); barrier; epilogue (pure LDS); barrier; commit bias(jt+1).
// ============================================================================
#define LG_BIAS 0                       // [64][136] f32 = 34816 (QH overlays at 0 in prologue)
#define LG_MB   34816                   // [64][4] u32 = 1024
#define LG_QL   35840                   // 8192
#define LG_KH   44032                   // 2 x 16384
#define LG_KL   76800                   // 2 x 16384
#define SMEM_LG 109568                  // x2 CTAs = 214KB

__global__ __launch_bounds__(256, 2) void logits_mma(const float* __restrict__ gbias) {
    extern __shared__ char smem[];
    const uint32_t sb = cvta_s(smem);
    const int tid = threadIdx.x;
    const int warp = tid >> 5, lane = tid & 31;
    const int bh = blockIdx.x;
    const int b  = bh >> 2, h = bh & 3;
    const int q0 = blockIdx.y * 64;
    const int qw = (warp >> 2) * 32;
    const int jw = (warp & 3) * 32;

    auto load_biasmb = [&](int jt) {
        #pragma unroll
        for (int k = 0; k < 8; k++) {
            int idx = tid + k*256;              // 2048 f4 chunks
            int row = idx >> 5, c4 = idx & 31;
            cp16(sb + LG_BIAS + (uint32_t)(row*544 + c4*16),
                 gbias + (size_t)(h*S + q0 + row)*S + jt*128 + c4*4);
        }
        if (tid < 64)
            cp16(sb + LG_MB + tid*16,
                 g_mbits + (size_t)(b*S + q0 + tid)*64 + jt*4);
    };

    { // prologue: QH(at 0) + QL + K0, one group
        const __nv_bfloat16* qh = g_qh + ((size_t)bh*S + q0)*DH;
        const __nv_bfloat16* ql = g_ql + ((size_t)bh*S + q0)*DH;
        #pragma unroll
        for (int k = 0; k < 2; k++) {
            int idx = tid + k*256;
            if (idx < 384) {
                int r = idx / 6, c = idx % 6;
                uint32_t off = r*128 + ((c ^ (r&7))<<4);
                cp16(sb + LG_BIAS + off, qh + r*DH + c*8);   // QH overlays bias area
                cp16(sb + LG_QL   + off, ql + r*DH + c*8);
            }
        }
        const __nv_bfloat16* kh = g_kh + (size_t)bh*S*DH;
        const __nv_bfloat16* kl = g_kl + (size_t)bh*S*DH;
        #pragma unroll
        for (int k = 0; k < 3; k++) {
            int idx = tid + k*256;
            int r = idx / 6, c = idx % 6;
            uint32_t off = r*128 + ((c ^ (r&7))<<4);
            cp16(sb + LG_KH + off, kh + r*DH + c*8);
            cp16(sb + LG_KL + off, kl + r*DH + c*8);
        }
        cp_commit();
    }
    cp_wait0();
    __syncthreads();

    uint32_t ah[2][3][4];
    #pragma unroll
    for (int mi = 0; mi < 2; mi++)
        #pragma unroll
        for (int ks = 0; ks < 3; ks++) {
            int r = qw + mi*16 + (lane & 7) + ((lane >> 3) & 1)*8;
            int c = ks*2 + (lane >> 4);
            ldsm4(sb + LG_BIAS + r*128 + ((c ^ (r&7))<<4), ah[mi][ks]);
        }
    __syncthreads();          // all warps done reading QH area
    load_biasmb(0);
    cp_commit();              // G_bias(0)

    float lsum[4] = {0.f, 0.f, 0.f, 0.f};

    for (int jt = 0; jt < 16; jt++) {
        const uint32_t kbH = sb + LG_KH + (jt & 1)*16384;
        const uint32_t kbL = sb + LG_KL + (jt & 1)*16384;

        if (jt + 1 < 16) {    // commit K(jt+1)
            const uint32_t nH = sb + LG_KH + ((jt+1) & 1)*16384;
            const uint32_t nL = sb + LG_KL + ((jt+1) & 1)*16384;
            const __nv_bfloat16* kh = g_kh + ((size_t)bh*S + (jt+1)*128)*DH;
            const __nv_bfloat16* kl = g_kl + ((size_t)bh*S + (jt+1)*128)*DH;
            #pragma unroll
            for (int k = 0; k < 3; k++) {
                int idx = tid + k*256;
                int r = idx / 6, c = idx % 6;
                uint32_t off = r*128 + ((c ^ (r&7))<<4);
                cp16(nH + off, kh + r*DH + c*8);
                cp16(nL + off, kl + r*DH + c*8);
            }
            cp_commit();
            cp_wait2();       // K(jt) landed (bias(jt), K(jt+1) may fly)
        } else {
            cp_wait1();       // K(15) landed
        }

        float acc[2][4][4];
        #pragma unroll
        for (int mi = 0; mi < 2; mi++)
            #pragma unroll
            for (int nj = 0; nj < 4; nj++)
                #pragma unroll
                for (int p = 0; p < 4; p++) acc[mi][nj][p] = 0.f;

        #pragma unroll
        for (int ks = 0; ks < 3; ks++) {
            uint32_t bhf[2][4], blf[2][4], alf[2][4];
            #pragma unroll
            for (int jj = 0; jj < 2; jj++) {
                int r = jw + jj*16 + (lane & 7) + (lane >> 4)*8;
                int c = ks*2 + ((lane >> 3) & 1);
                uint32_t off = r*128 + ((c ^ (r&7))<<4);
                ldsm4(kbH + off, bhf[jj]);
                ldsm4(kbL + off, blf[jj]);
            }
            #pragma unroll
            for (int mi = 0; mi < 2; mi++) {
                int r = qw + mi*16 + (lane & 7) + ((lane >> 3) & 1)*8;
                int c = ks*2 + (lane >> 4);
                ldsm4(sb + LG_QL + r*128 + ((c ^ (r&7))<<4), alf[mi]);
            }
            #pragma unroll
            for (int mi = 0; mi < 2; mi++)
                #pragma unroll
                for (int jj = 0; jj < 2; jj++)
                    #pragma unroll
                    for (int sub = 0; sub < 2; sub++) {
                        float* a = acc[mi][jj*2 + sub];
                        mma16816(a, ah[mi][ks], &bhf[jj][sub*2]);
                        mma16816(a, ah[mi][ks], &blf[jj][sub*2]);
                        mma16816(a, alf[mi],    &bhf[jj][sub*2]);
                    }
        }

        if (jt + 1 < 16) cp_wait1();   // bias(jt) landed
        else             cp_wait0();
        __syncthreads();               // K-reuse + bias visibility

        // epilogue: pure smem reads
        const int jvbase = jt*128 + jw + 8*(lane & 3);
        const int bit0 = (lane & 3)*2;
        const float* sB = reinterpret_cast<const float*>(smem + LG_BIAS);
        const uint32_t* sM = reinterpret_cast<const uint32_t*>(smem + LG_MB);
        #pragma unroll
        for (int mi = 0; mi < 2; mi++)
            #pragma unroll
            for (int h2 = 0; h2 < 2; h2++) {
                const int qrl = qw + mi*16 + h2*8 + (lane >> 2);
                const uint32_t mw = sM[qrl*4 + (warp & 3)];         // quad broadcast
                const float* bp = sB + qrl*136 + jw + (lane & 3)*2;
                float ls = 0.f;
                uint32_t hw[4], lw[4];
                #pragma unroll
                for (int nj = 0; nj < 4; nj++) {
                    float2 bv = *reinterpret_cast<const float2*>(bp + nj*8);
                    bool m0 = (mw >> (bit0 + nj*8)) & 1u;
                    bool m1 = (mw >> (bit0 + nj*8 + 1)) & 1u;
                    float e0 = fexp(m0 ? acc[mi][nj][h2*2+0] + bv.x : NEG_INF);
                    float e1 = fexp(m1 ? acc[mi][nj][h2*2+1] + bv.y : NEG_INF);
                    uint32_t hp = cvt2bf(e0, e1);
                    float hx = __uint_as_float(hp << 16);
                    float hy = __uint_as_float(hp & 0xFFFF0000u);
                    uint32_t lp = cvt2bf(e0 - hx, e1 - hy);
                    hw[nj] = hp;
                    lw[nj] = lp;
                    ls += e0 + e1;
                }
                const int qrow = q0 + qrl;
                uint4 hq; hq.x = hw[0]; hq.y = hw[1]; hq.z = hw[2]; hq.w = hw[3];
                uint4 lq; lq.x = lw[0]; lq.y = lw[1]; lq.z = lw[2]; lq.w = lw[3];
                *reinterpret_cast<uint4*>(g_Eh + ((size_t)bh*S + qrow)*S + jvbase) = hq;
                *reinterpret_cast<uint4*>(g_El + ((size_t)bh*S + qrow)*S + jvbase) = lq;
                lsum[mi*2 + h2] += ls;
            }

        __syncthreads();               // all done reading bias before rewrite
        if (jt + 1 < 16) {
            load_biasmb(jt + 1);
            cp_commit();               // G_bias(jt+1)
        }
    }

    // rowsum reduce (sums alias the bias area — free after last barrier)
    float (*sums)[4] = reinterpret_cast<float(*)[4]>(smem);
    #pragma unroll
    for (int k = 0; k < 4; k++) {
        float v = lsum[k];
        v += __shfl_xor_sync(0xffffffffu, v, 1);
        v += __shfl_xor_sync(0xffffffffu, v, 2);
        if ((lane & 3) == 0)
            sums[qw + (k >> 1)*16 + (k & 1)*8 + (lane >> 2)][warp & 3] = v;
    }
    __syncthreads();
    if (tid < 64) {
        float L = sums[tid][0] + sums[tid][1] + sums[tid][2] + sums[tid][3];
        g_Linv[(size_t)bh*S + q0 + tid] = 1.0f / L;
    }
}

// ============================================================================
// pv_mma: DEPTH-3 cp.async pipeline (R15 version, unchanged)
// ============================================================================
#define PM_OFF_LINV 33792
#define PM_OFF_TILE 34816
#define PM_BUF 65536
#define PM_EH 0
#define PM_EL 16384
#define PM_VH 32768
#define PM_VL 49152
#define SMEM_PV (PM_OFF_TILE + 3*PM_BUF)

__global__ __launch_bounds__(256, 1) void pv_mma(float* __restrict__ om) {
    extern __shared__ char smem[];
    const uint32_t sb = cvta_s(smem);
    float* sMean  = reinterpret_cast<float*>(smem);
    float* sLinvf = reinterpret_cast<float*>(smem + PM_OFF_LINV);
    const int tid = threadIdx.x;
    const int warp = tid >> 5, lane = tid & 31;
    const int b  = blockIdx.x;
    const int q0 = blockIdx.y * 64;
    const int q0w = (warp >> 1) * 16;
    const int wd  = warp & 1;
    const int cV  = wd * 3;

    {
        int hh = tid >> 6, q = tid & 63;
        sLinvf[tid] = g_Linv[(size_t)(b*H + hh)*S + q0 + q];
    }

    auto load_stage = [&](int st, uint32_t bufb) {
        const int jt = st >> 2, hh = st & 3;
        const int bhl = b*H + hh;
        const __nv_bfloat16* ehp = g_Eh + ((size_t)bhl*S + q0)*S + jt*128;
        const __nv_bfloat16* elp = g_El + ((size_t)bhl*S + q0)*S + jt*128;
        #pragma unroll
        for (int k = 0; k < 4; k++) {
            int idx = tid + k*256;
            int r = idx >> 4, cj = idx & 15;
            uint32_t off = r*256 + ((cj ^ (r&7))<<4);
            cp16(bufb + PM_EH + off, ehp + (size_t)r*S + cj*8);
            cp16(bufb + PM_EL + off, elp + (size_t)r*S + cj*8);
        }
        const __nv_bfloat16* vhp = g_vh + ((size_t)bhl*S + jt*128)*DH;
        const __nv_bfloat16* vlp = g_vl + ((size_t)bhl*S + jt*128)*DH;
        #pragma unroll
        for (int k = 0; k < 3; k++) {
            int idx = tid + k*256;
            int r = idx / 6, c = idx % 6;
            int vr = (r & 96) | (8*((r&7)>>1) + 2*((r>>3)&3) + (r&1));
            uint32_t off = vr*128 + ((c ^ (vr&7))<<4);
            cp16(bufb + PM_VH + off, vhp + r*DH + c*8);
            cp16(bufb + PM_VL + off, vlp + r*DH + c*8);
        }
    };

    load_stage(0, sb + PM_OFF_TILE + 0*PM_BUF);
    cp_commit();
    load_stage(1, sb + PM_OFF_TILE + 1*PM_BUF);
    cp_commit();
    __syncthreads();

    float acc[4][3][4];
    #pragma unroll
    for (int hh = 0; hh < 4; hh++)
        #pragma unroll
        for (int nt = 0; nt < 3; nt++)
            #pragma unroll
            for (int p = 0; p < 4; p++) acc[hh][nt][p] = 0.f;

    for (int jt = 0; jt < 16; jt++) {
        #pragma unroll
        for (int hh = 0; hh < 4; hh++) {
            const int st = jt*4 + hh;
            if (st + 2 < 64) {
                load_stage(st + 2, sb + PM_OFF_TILE + ((st+2) % 3)*PM_BUF);
                cp_commit();
                cp_wait2();
            } else {
                cp_wait0();
            }
            __syncthreads();
            const uint32_t tb = sb + PM_OFF_TILE + (st % 3)*PM_BUF;
            const char*   tbp = smem + PM_OFF_TILE + (st % 3)*PM_BUF;

            #pragma unroll
            for (int k = 0; k < 4; k++) {
                int idx = tid + k*256;
                int q = idx >> 4, cj = idx & 15;
                uint32_t eoff = q*256 + ((cj ^ (q&7))<<4);
                uint4 uh = *reinterpret_cast<const uint4*>(tbp + PM_EH + eoff);
                uint4 ul = *reinterpret_cast<const uint4*>(tbp + PM_EL + eoff);
                float linv = sLinvf[hh*64 + q];
                float2 f0 = __bfloat1622float2(*reinterpret_cast<__nv_bfloat162*>(&uh.x));
                float2 f1 = __bfloat1622float2(*reinterpret_cast<__nv_bfloat162*>(&uh.y));
                float2 f2 = __bfloat1622float2(*reinterpret_cast<__nv_bfloat162*>(&uh.z));
                float2 f3 = __bfloat1622float2(*reinterpret_cast<__nv_bfloat162*>(&uh.w));
                float2 g0 = __bfloat1622float2(*reinterpret_cast<__nv_bfloat162*>(&ul.x));
                float2 g1 = __bfloat1622float2(*reinterpret_cast<__nv_bfloat162*>(&ul.y));
                float2 g2 = __bfloat1622float2(*reinterpret_cast<__nv_bfloat162*>(&ul.z));
                float2 g3 = __bfloat1622float2(*reinterpret_cast<__nv_bfloat162*>(&ul.w));
                float* mp = sMean + q*132 + cj*8;
                if (hh == 0) {
                    float4 m0, m1;
                    m0.x = (f0.x+g0.x)*linv; m0.y = (f0.y+g0.y)*linv;
                    m0.z = (f1.x+g1.x)*linv; m0.w = (f1.y+g1.y)*linv;
                    m1.x = (f2.x+g2.x)*linv; m1.y = (f2.y+g2.y)*linv;
                    m1.z = (f3.x+g3.x)*linv; m1.w = (f3.y+g3.y)*linv;
                    *reinterpret_cast<float4*>(mp)     = m0;
                    *reinterpret_cast<float4*>(mp + 4) = m1;
                } else {
                    float4 m0 = *reinterpret_cast<float4*>(mp);
                    float4 m1 = *reinterpret_cast<float4*>(mp + 4);
                    m0.x += (f0.x+g0.x)*linv; m0.y += (f0.y+g0.y)*linv;
                    m0.z += (f1.x+g1.x)*linv; m0.w += (f1.y+g1.y)*linv;
                    m1.x += (f2.x+g2.x)*linv; m1.y += (f2.y+g2.y)*linv;
                    m1.z += (f3.x+g3.x)*linv; m1.w += (f3.y+g3.y)*linv;
                    *reinterpret_cast<float4*>(mp)     = m0;
                    *reinterpret_cast<float4*>(mp + 4) = m1;
                }
            }

            #pragma unroll
            for (int ks = 0; ks < 8; ks++) {
                int ra = q0w + (lane & 15);
                int ca = ks*2 + (lane >> 4);
                uint32_t aoff = ra*256 + ((ca ^ (ra&7))<<4);
                uint32_t ahf[4], alf[4];
                ldsm4(tb + PM_EH + aoff, ahf);
                ldsm4(tb + PM_EL + aoff, alf);

                int rb = ks*16 + (lane & 15);
                int cb4 = cV + (lane >> 4);
                uint32_t boff4 = rb*128 + ((cb4 ^ (rb&7))<<4);
                uint32_t bh4[4], bl4[4];
                ldsm4t(tb + PM_VH + boff4, bh4);
                ldsm4t(tb + PM_VL + boff4, bl4);
                int cb2 = cV + 2;
                uint32_t boff2 = rb*128 + ((cb2 ^ (rb&7))<<4);
                uint32_t bh2[2], bl2[2];
                ldsm2t(tb + PM_VH + boff2, bh2);
                ldsm2t(tb + PM_VL + boff2, bl2);

                #pragma unroll
                for (int nt = 0; nt < 2; nt++) {
                    float* a = acc[hh][nt];
                    mma16816(a, ahf, &bh4[nt*2]);
                    mma16816(a, ahf, &bl4[nt*2]);
                    mma16816(a, alf, &bh4[nt*2]);
                }
                {
                    float* a = acc[hh][2];
                    mma16816(a, ahf, bh2);
                    mma16816(a, ahf, bl2);
                    mma16816(a, alf, bh2);
                }
            }

            if (hh == 3) {
                __syncthreads();
                #pragma unroll
                for (int k = 0; k < 8; k++) {
                    int idx = tid + k*256;
                    int q = idx >> 5, c4 = idx & 31;
                    int g = (c4 >> 3) << 5;
                    int r32 = (4*c4) & 31;
                    int v0 = g + 8*((r32 & 7) >> 1) + 2*(r32 >> 3);
                    float2 m0 = *reinterpret_cast<const float2*>(sMean + q*132 + v0);
                    float2 m1 = *reinterpret_cast<const float2*>(sMean + q*132 + v0 + 8);
                    float4 r;
                    r.x = 0.25f*m0.x; r.y = 0.25f*m0.y;
                    r.z = 0.25f*m1.x; r.w = 0.25f*m1.y;
                    *reinterpret_cast<float4*>(om + (size_t)(b*S + q0 + q)*S + jt*128 + c4*4) = r;
                }
            }
            __syncthreads();
        }
    }

    #pragma unroll
    for (int hh = 0; hh < 4; hh++) {
        const int row0 = q0w + (lane >> 2);
        const float l0 = sLinvf[hh*64 + row0];
        const float l1 = sLinvf[hh*64 + row0 + 8];
        #pragma unroll
        for (int nt = 0; nt < 3; nt++) {
            const int col = hh*48 + wd*24 + nt*8 + (lane & 3)*2;
            float2 o0; o0.x = acc[hh][nt][0]*l0; o0.y = acc[hh][nt][1]*l0;
            float2 o1; o1.x = acc[hh][nt][2]*l1; o1.y = acc[hh][nt][3]*l1;
            *reinterpret_cast<float2*>(g_ctx + (size_t)(b*S + q0 + row0)*D + col)     = o0;
            *reinterpret_cast<float2*>(g_ctx + (size_t)(b*S + q0 + row0 + 8)*D + col) = o1;
        }
    }
}

extern "C" void kernel_launch(void* const* d_in, const int* in_sizes, int n_in,
                              void* d_out, int out_size) {
    (void)in_sizes; (void)n_in; (void)out_size;
    const float* query = (const float*)d_in[0];
    const float* key   = (const float*)d_in[1];
    const float* value = (const float*)d_in[2];
    const int*   mask  = (const int*)  d_in[3];
    const float* bias  = (const float*)d_in[4];
    const float* Wq    = (const float*)d_in[5];
    const float* Wk    = (const float*)d_in[6];
    const float* Wv    = (const float*)d_in[7];
    const float* Wo    = (const float*)d_in[8];

    float* out = (float*)d_out;                 // [B,S,D]
    float* om  = out + B*S*D;                   // [B,S,S] mean weights

    float *pctx;
    cudaGetSymbolAddress((void**)&pctx, g_ctx);

    cudaFuncSetAttribute(logits_mma, cudaFuncAttributeMaxDynamicSharedMemorySize, SMEM_LG);
    cudaFuncSetAttribute(pv_mma,     cudaFuncAttributeMaxDynamicSharedMemorySize, SMEM_PV);

    transpose_w<<<dim3(6,6,4), dim3(32,8)>>>(Wq, Wk, Wv, Wo);
    mbits_kernel<<<(B*S)/8, 256>>>(mask);
    proj3_kernel<<<dim3(256,3), 128>>>(query, key, value);
    logits_mma<<<dim3(B*H, S/64), 256, SMEM_LG>>>(bias);
    pv_mma<<<dim3(B, S/64), 256, SMEM_PV>>>(om);
    proj1_kernel<<<dim3(256,1), 128>>>(pctx, out);
}

// round 17
// speedup vs baseline: 1.2252x; 1.0747x over previous
#include <cuda_runtime.h>
#include <cuda_bf16.h>
#include <cstdint>

#define B 4
#define S 2048
#define H 4
#define DH 48
#define D 192
#define NEG_INF -1000000000.0f

// Scratch
__device__ float g_ctx[B*S*D];
__device__ float g_Linv[B*H*S];
__device__ float g_WT[4][D*D];
__device__ uint32_t g_mbits[B*S*64];           // bit-packed mask (2MB)
__device__ __nv_bfloat16 g_qh[B*H*S*DH];
__device__ __nv_bfloat16 g_ql[B*H*S*DH];
__device__ __nv_bfloat16 g_kh[B*H*S*DH];
__device__ __nv_bfloat16 g_kl[B*H*S*DH];
__device__ __nv_bfloat16 g_vh[B*H*S*DH];
__device__ __nv_bfloat16 g_vl[B*H*S*DH];
// E stored j-PERMUTED (fragment-native): within each 32-j group,
// actual a = 2p + 8t + u  <->  virtual v = 8p + 2t + u.
__device__ __nv_bfloat16 g_Eh[(size_t)B*H*S*S];
__device__ __nv_bfloat16 g_El[(size_t)B*H*S*S];

// ---------- packed fp32x2 helpers ----------
__device__ __forceinline__ unsigned long long pack2(float x, float y) {
    unsigned long long r;
    asm("mov.b64 %0, {%1,%2};" : "=l"(r) : "f"(x), "f"(y));
    return r;
}
__device__ __forceinline__ void unpack2(unsigned long long v, float& x, float& y) {
    asm("mov.b64 {%0,%1}, %2;" : "=f"(x), "=f"(y) : "l"(v));
}
__device__ __forceinline__ void ffma2(unsigned long long& d, unsigned long long a, unsigned long long b) {
    asm("fma.rn.f32x2 %0, %1, %2, %0;" : "+l"(d) : "l"(a), "l"(b));
}

// ---------- fast exp on the FMA pipe ----------
__device__ __forceinline__ float fexp(float x) {
    float y = fmaxf(x * 1.44269504f, -126.0f);
    float t = y + 12582912.0f;
    float f = y - (t - 12582912.0f);
    int   e = __float_as_int(t) - 0x4B400000;
    float s = __int_as_float((e + 127) << 23);
    float p =              1.3333558e-3f;
    p = fmaf(p, f, 9.6181291e-3f);
    p = fmaf(p, f, 5.5504109e-2f);
    p = fmaf(p, f, 2.4022651e-1f);
    p = fmaf(p, f, 6.9314718e-1f);
    p = fmaf(p, f, 1.0f);
    return p * s;
}

// packed bf16x2 convert: lo16 = cvt(a), hi16 = cvt(b)
__device__ __forceinline__ uint32_t cvt2bf(float a, float b) {
    uint32_t r;
    asm("cvt.rn.bf16x2.f32 %0, %1, %2;" : "=r"(r) : "f"(b), "f"(a));
    return r;
}

// ---------- cp.async helpers ----------
__device__ __forceinline__ void cp16(uint32_t saddr, const void* gptr) {
    asm volatile("cp.async.cg.shared.global [%0], [%1], 16;" :: "r"(saddr), "l"(gptr));
}
__device__ __forceinline__ void cp_commit() { asm volatile("cp.async.commit_group;"); }
__device__ __forceinline__ void cp_wait2()  { asm volatile("cp.async.wait_group 2;"); }
__device__ __forceinline__ void cp_wait1()  { asm volatile("cp.async.wait_group 1;"); }
__device__ __forceinline__ void cp_wait0()  { asm volatile("cp.async.wait_group 0;"); }
__device__ __forceinline__ uint32_t cvta_s(const void* p) {
    return (uint32_t)__cvta_generic_to_shared(p);
}

// ---------- mma.sync / ldmatrix helpers ----------
__device__ __forceinline__ void ldsm4(uint32_t addr, uint32_t* r) {
    asm volatile("ldmatrix.sync.aligned.m8n8.x4.shared.b16 {%0,%1,%2,%3}, [%4];"
                 : "=r"(r[0]), "=r"(r[1]), "=r"(r[2]), "=r"(r[3]) : "r"(addr));
}
__device__ __forceinline__ void ldsm4t(uint32_t addr, uint32_t* r) {
    asm volatile("ldmatrix.sync.aligned.m8n8.x4.trans.shared.b16 {%0,%1,%2,%3}, [%4];"
                 : "=r"(r[0]), "=r"(r[1]), "=r"(r[2]), "=r"(r[3]) : "r"(addr));
}
__device__ __forceinline__ void ldsm2t(uint32_t addr, uint32_t* r) {
    asm volatile("ldmatrix.sync.aligned.m8n8.x2.trans.shared.b16 {%0,%1}, [%2];"
                 : "=r"(r[0]), "=r"(r[1]) : "r"(addr));
}
__device__ __forceinline__ void mma16816(float* c, const uint32_t* a, const uint32_t* b) {
    asm volatile("mma.sync.aligned.m16n8k16.row.col.f32.bf16.bf16.f32 "
                 "{%0,%1,%2,%3}, {%4,%5,%6,%7}, {%8,%9}, {%0,%1,%2,%3};"
                 : "+f"(c[0]), "+f"(c[1]), "+f"(c[2]), "+f"(c[3])
                 : "r"(a[0]), "r"(a[1]), "r"(a[2]), "r"(a[3]), "r"(b[0]), "r"(b[1]));
}

// ---------- mask -> bit pack ----------
__global__ __launch_bounds__(256) void mbits_kernel(const int* __restrict__ m) {
    const int row = blockIdx.x*8 + (threadIdx.x >> 5);
    const int lane = threadIdx.x & 31;
    const int* mr = m + (size_t)row * S;
    uint32_t w0 = 0, w1 = 0;
    #pragma unroll 4
    for (int it = 0; it < 64; it++) {
        uint32_t bal = __ballot_sync(0xffffffffu, mr[it*32 + lane] != 0);
        if ((it & 31) == lane) { if (it < 32) w0 = bal; else w1 = bal; }
    }
    g_mbits[(size_t)row*64 + lane]      = w0;
    g_mbits[(size_t)row*64 + 32 + lane] = w1;
}

// ---------- weight transpose ----------
__global__ void transpose_w(const float* __restrict__ W0, const float* __restrict__ W1,
                            const float* __restrict__ W2, const float* __restrict__ W3) {
    __shared__ float tile[32][33];
    const float* W = (blockIdx.z == 0) ? W0 : (blockIdx.z == 1) ? W1 : (blockIdx.z == 2) ? W2 : W3;
    float* WT = g_WT[blockIdx.z];
    int x = blockIdx.x*32 + threadIdx.x;
    int y = blockIdx.y*32 + threadIdx.y;
    #pragma unroll
    for (int j = 0; j < 32; j += 8)
        tile[threadIdx.y + j][threadIdx.x] = W[(y + j)*D + x];
    __syncthreads();
    int x2 = blockIdx.y*32 + threadIdx.x;
    int y2 = blockIdx.x*32 + threadIdx.y;
    #pragma unroll
    for (int j = 0; j < 32; j += 8)
        WT[(y2 + j)*D + x2] = tile[threadIdx.x][threadIdx.y + j];
}

// ---------- projection core ----------
template<bool BF16OUT>
__device__ __forceinline__ void proj_core(const float* __restrict__ X,
                                          const float* __restrict__ WT,
                                          float* __restrict__ Yf,
                                          __nv_bfloat16* __restrict__ Yh,
                                          __nv_bfloat16* __restrict__ Yl,
                                          int r0) {
    __shared__ float sXT[192*33];
    const int tid = threadIdx.x;
    const int w = tid >> 5, lane = tid & 31;

    #pragma unroll
    for (int k = 0; k < 12; k++) {
        int idx = tid + k*128;
        int r = idx / 48, c = idx % 48;
        float4 v = *reinterpret_cast<const float4*>(X + (size_t)(r0 + r)*D + 4*c);
        sXT[(4*c+0)*33 + r] = v.x;
        sXT[(4*c+1)*33 + r] = v.y;
        sXT[(4*c+2)*33 + r] = v.z;
        sXT[(4*c+3)*33 + r] = v.w;
    }
    __syncthreads();

    unsigned long long acc[8][3];
    #pragma unroll
    for (int i = 0; i < 8; i++)
        #pragma unroll
        for (int p = 0; p < 3; p++) acc[i][p] = 0ull;

    #pragma unroll 2
    for (int k = 0; k < 192; k++) {
        const unsigned long long* wrow =
            reinterpret_cast<const unsigned long long*>(WT + k*D + lane*6);
        unsigned long long w0 = wrow[0], w1 = wrow[1], w2 = wrow[2];
        #pragma unroll
        for (int i = 0; i < 8; i++) {
            float xv = sXT[k*33 + w*8 + i];
            unsigned long long x2 = pack2(xv, xv);
            ffma2(acc[i][0], x2, w0);
            ffma2(acc[i][1], x2, w1);
            ffma2(acc[i][2], x2, w2);
        }
    }
    #pragma unroll
    for (int i = 0; i < 8; i++) {
        const int row = r0 + w*8 + i;
        if (BF16OUT) {
            const int bb = row >> 11, s = row & 2047;
            const int hh = lane >> 3, c0 = (lane & 7)*6;
            size_t base = ((size_t)(bb*H + hh)*S + s)*DH + c0;
            #pragma unroll
            for (int m = 0; m < 3; m++) {
                float x, y; unpack2(acc[i][m], x, y);
                __nv_bfloat16 hx = __float2bfloat16(x);
                __nv_bfloat16 hy = __float2bfloat16(y);
                float lx = x - __bfloat162float(hx);
                float ly = y - __bfloat162float(hy);
                __nv_bfloat162 hv; hv.x = hx; hv.y = hy;
                __nv_bfloat162 lv; lv.x = __float2bfloat16(lx); lv.y = __float2bfloat16(ly);
                *reinterpret_cast<__nv_bfloat162*>(Yh + base + 2*m) = hv;
                *reinterpret_cast<__nv_bfloat162*>(Yl + base + 2*m) = lv;
            }
        } else {
            unsigned long long* dst =
                reinterpret_cast<unsigned long long*>(Yf + (size_t)row*D + lane*6);
            dst[0] = acc[i][0]; dst[1] = acc[i][1]; dst[2] = acc[i][2];
        }
    }
}

__global__ __launch_bounds__(128, 4) void proj3_kernel(const float* __restrict__ Xq,
                                                       const float* __restrict__ Xk,
                                                       const float* __restrict__ Xv) {
    const int which = blockIdx.y;
    const int r0 = blockIdx.x * 32;
    if (which == 2)      proj_core<true >(Xv, g_WT[2], nullptr, g_vh, g_vl, r0);
    else if (which == 0) proj_core<true >(Xq, g_WT[0], nullptr, g_qh, g_ql, r0);
    else                 proj_core<true >(Xk, g_WT[1], nullptr, g_kh, g_kl, r0);
}

__global__ __launch_bounds__(128, 4) void proj1_kernel(const float* __restrict__ X,
                                                       float* __restrict__ Y) {
    proj_core<false>(X, g_WT[3], Y, nullptr, nullptr, blockIdx.x * 32);
}

// ============================================================================
// logits_mma (R16: fully smem-staged epilogue — unchanged)
// ============================================================================
#define LG_BIAS 0
#define LG_MB   34816
#define LG_QL   35840
#define LG_KH   44032
#define LG_KL   76800
#define SMEM_LG 109568

__global__ __launch_bounds__(256, 2) void logits_mma(const float* __restrict__ gbias) {
    extern __shared__ char smem[];
    const uint32_t sb = cvta_s(smem);
    const int tid = threadIdx.x;
    const int warp = tid >> 5, lane = tid & 31;
    const int bh = blockIdx.x;
    const int b  = bh >> 2, h = bh & 3;
    const int q0 = blockIdx.y * 64;
    const int qw = (warp >> 2) * 32;
    const int jw = (warp & 3) * 32;

    auto load_biasmb = [&](int jt) {
        #pragma unroll
        for (int k = 0; k < 8; k++) {
            int idx = tid + k*256;
            int row = idx >> 5, c4 = idx & 31;
            cp16(sb + LG_BIAS + (uint32_t)(row*544 + c4*16),
                 gbias + (size_t)(h*S + q0 + row)*S + jt*128 + c4*4);
        }
        if (tid < 64)
            cp16(sb + LG_MB + tid*16,
                 g_mbits + (size_t)(b*S + q0 + tid)*64 + jt*4);
    };

    {
        const __nv_bfloat16* qh = g_qh + ((size_t)bh*S + q0)*DH;
        const __nv_bfloat16* ql = g_ql + ((size_t)bh*S + q0)*DH;
        #pragma unroll
        for (int k = 0; k < 2; k++) {
            int idx = tid + k*256;
            if (idx < 384) {
                int r = idx / 6, c = idx % 6;
                uint32_t off = r*128 + ((c ^ (r&7))<<4);
                cp16(sb + LG_BIAS + off, qh + r*DH + c*8);
                cp16(sb + LG_QL   + off, ql + r*DH + c*8);
            }
        }
        const __nv_bfloat16* kh = g_kh + (size_t)bh*S*DH;
        const __nv_bfloat16* kl = g_kl + (size_t)bh*S*DH;
        #pragma unroll
        for (int k = 0; k < 3; k++) {
            int idx = tid + k*256;
            int r = idx / 6, c = idx % 6;
            uint32_t off = r*128 + ((c ^ (r&7))<<4);
            cp16(sb + LG_KH + off, kh + r*DH + c*8);
            cp16(sb + LG_KL + off, kl + r*DH + c*8);
        }
        cp_commit();
    }
    cp_wait0();
    __syncthreads();

    uint32_t ah[2][3][4];
    #pragma unroll
    for (int mi = 0; mi < 2; mi++)
        #pragma unroll
        for (int ks = 0; ks < 3; ks++) {
            int r = qw + mi*16 + (lane & 7) + ((lane >> 3) & 1)*8;
            int c = ks*2 + (lane >> 4);
            ldsm4(sb + LG_BIAS + r*128 + ((c ^ (r&7))<<4), ah[mi][ks]);
        }
    __syncthreads();
    load_biasmb(0);
    cp_commit();

    float lsum[4] = {0.f, 0.f, 0.f, 0.f};

    for (int jt = 0; jt < 16; jt++) {
        const uint32_t kbH = sb + LG_KH + (jt & 1)*16384;
        const uint32_t kbL = sb + LG_KL + (jt & 1)*16384;

        if (jt + 1 < 16) {
            const uint32_t nH = sb + LG_KH + ((jt+1) & 1)*16384;
            const uint32_t nL = sb + LG_KL + ((jt+1) & 1)*16384;
            const __nv_bfloat16* kh = g_kh + ((size_t)bh*S + (jt+1)*128)*DH;
            const __nv_bfloat16* kl = g_kl + ((size_t)bh*S + (jt+1)*128)*DH;
            #pragma unroll
            for (int k = 0; k < 3; k++) {
                int idx = tid + k*256;
                int r = idx / 6, c = idx % 6;
                uint32_t off = r*128 + ((c ^ (r&7))<<4);
                cp16(nH + off, kh + r*DH + c*8);
                cp16(nL + off, kl + r*DH + c*8);
            }
            cp_commit();
            cp_wait2();
        } else {
            cp_wait1();
        }

        float acc[2][4][4];
        #pragma unroll
        for (int mi = 0; mi < 2; mi++)
            #pragma unroll
            for (int nj = 0; nj < 4; nj++)
                #pragma unroll
                for (int p = 0; p < 4; p++) acc[mi][nj][p] = 0.f;

        #pragma unroll
        for (int ks = 0; ks < 3; ks++) {
            uint32_t bhf[2][4], blf[2][4], alf[2][4];
            #pragma unroll
            for (int jj = 0; jj < 2; jj++) {
                int r = jw + jj*16 + (lane & 7) + (lane >> 4)*8;
                int c = ks*2 + ((lane >> 3) & 1);
                uint32_t off = r*128 + ((c ^ (r&7))<<4);
                ldsm4(kbH + off, bhf[jj]);
                ldsm4(kbL + off, blf[jj]);
            }
            #pragma unroll
            for (int mi = 0; mi < 2; mi++) {
                int r = qw + mi*16 + (lane & 7) + ((lane >> 3) & 1)*8;
                int c = ks*2 + (lane >> 4);
                ldsm4(sb + LG_QL + r*128 + ((c ^ (r&7))<<4), alf[mi]);
            }
            #pragma unroll
            for (int mi = 0; mi < 2; mi++)
                #pragma unroll
                for (int jj = 0; jj < 2; jj++)
                    #pragma unroll
                    for (int sub = 0; sub < 2; sub++) {
                        float* a = acc[mi][jj*2 + sub];
                        mma16816(a, ah[mi][ks], &bhf[jj][sub*2]);
                        mma16816(a, ah[mi][ks], &blf[jj][sub*2]);
                        mma16816(a, alf[mi],    &bhf[jj][sub*2]);
                    }
        }

        if (jt + 1 < 16) cp_wait1();
        else             cp_wait0();
        __syncthreads();

        const int jvbase = jt*128 + jw + 8*(lane & 3);
        const int bit0 = (lane & 3)*2;
        const float* sB = reinterpret_cast<const float*>(smem + LG_BIAS);
        const uint32_t* sM = reinterpret_cast<const uint32_t*>(smem + LG_MB);
        #pragma unroll
        for (int mi = 0; mi < 2; mi++)
            #pragma unroll
            for (int h2 = 0; h2 < 2; h2++) {
                const int qrl = qw + mi*16 + h2*8 + (lane >> 2);
                const uint32_t mw = sM[qrl*4 + (warp & 3)];
                const float* bp = sB + qrl*136 + jw + (lane & 3)*2;
                float ls = 0.f;
                uint32_t hw[4], lw[4];
                #pragma unroll
                for (int nj = 0; nj < 4; nj++) {
                    float2 bv = *reinterpret_cast<const float2*>(bp + nj*8);
                    bool m0 = (mw >> (bit0 + nj*8)) & 1u;
                    bool m1 = (mw >> (bit0 + nj*8 + 1)) & 1u;
                    float e0 = fexp(m0 ? acc[mi][nj][h2*2+0] + bv.x : NEG_INF);
                    float e1 = fexp(m1 ? acc[mi][nj][h2*2+1] + bv.y : NEG_INF);
                    uint32_t hp = cvt2bf(e0, e1);
                    float hx = __uint_as_float(hp << 16);
                    float hy = __uint_as_float(hp & 0xFFFF0000u);
                    uint32_t lp = cvt2bf(e0 - hx, e1 - hy);
                    hw[nj] = hp;
                    lw[nj] = lp;
                    ls += e0 + e1;
                }
                const int qrow = q0 + qrl;
                uint4 hq; hq.x = hw[0]; hq.y = hw[1]; hq.z = hw[2]; hq.w = hw[3];
                uint4 lq; lq.x = lw[0]; lq.y = lw[1]; lq.z = lw[2]; lq.w = lw[3];
                *reinterpret_cast<uint4*>(g_Eh + ((size_t)bh*S + qrow)*S + jvbase) = hq;
                *reinterpret_cast<uint4*>(g_El + ((size_t)bh*S + qrow)*S + jvbase) = lq;
                lsum[mi*2 + h2] += ls;
            }

        __syncthreads();
        if (jt + 1 < 16) {
            load_biasmb(jt + 1);
            cp_commit();
        }
    }

    float (*sums)[4] = reinterpret_cast<float(*)[4]>(smem);
    #pragma unroll
    for (int k = 0; k < 4; k++) {
        float v = lsum[k];
        v += __shfl_xor_sync(0xffffffffu, v, 1);
        v += __shfl_xor_sync(0xffffffffu, v, 2);
        if ((lane & 3) == 0)
            sums[qw + (k >> 1)*16 + (k & 1)*8 + (lane >> 2)][warp & 3] = v;
    }
    __syncthreads();
    if (tid < 64) {
        float L = sums[tid][0] + sums[tid][1] + sums[tid][2] + sums[tid][3];
        g_Linv[(size_t)bh*S + q0 + tid] = 1.0f / L;
    }
}

// ============================================================================
// pv_mma: depth-3 pipeline; head-mean accumulated in REGISTERS across the 4
// heads (macc[4][8]) and written to sMean once per jt — removes the per-stage
// sMean read-modify-write that dominated L1 traffic.
// ============================================================================
#define PM_OFF_LINV 33792
#define PM_OFF_TILE 34816
#define PM_BUF 65536
#define PM_EH 0
#define PM_EL 16384
#define PM_VH 32768
#define PM_VL 49152
#define SMEM_PV (PM_OFF_TILE + 3*PM_BUF)

__global__ __launch_bounds__(256, 1) void pv_mma(float* __restrict__ om) {
    extern __shared__ char smem[];
    const uint32_t sb = cvta_s(smem);
    float* sMean  = reinterpret_cast<float*>(smem);
    float* sLinvf = reinterpret_cast<float*>(smem + PM_OFF_LINV);
    const int tid = threadIdx.x;
    const int warp = tid >> 5, lane = tid & 31;
    const int b  = blockIdx.x;
    const int q0 = blockIdx.y * 64;
    const int q0w = (warp >> 1) * 16;
    const int wd  = warp & 1;
    const int cV  = wd * 3;

    {
        int hh = tid >> 6, q = tid & 63;
        sLinvf[tid] = g_Linv[(size_t)(b*H + hh)*S + q0 + q];
    }

    auto load_stage = [&](int st, uint32_t bufb) {
        const int jt = st >> 2, hh = st & 3;
        const int bhl = b*H + hh;
        const __nv_bfloat16* ehp = g_Eh + ((size_t)bhl*S + q0)*S + jt*128;
        const __nv_bfloat16* elp = g_El + ((size_t)bhl*S + q0)*S + jt*128;
        #pragma unroll
        for (int k = 0; k < 4; k++) {
            int idx = tid + k*256;
            int r = idx >> 4, cj = idx & 15;
            uint32_t off = r*256 + ((cj ^ (r&7))<<4);
            cp16(bufb + PM_EH + off, ehp + (size_t)r*S + cj*8);
            cp16(bufb + PM_EL + off, elp + (size_t)r*S + cj*8);
        }
        const __nv_bfloat16* vhp = g_vh + ((size_t)bhl*S + jt*128)*DH;
        const __nv_bfloat16* vlp = g_vl + ((size_t)bhl*S + jt*128)*DH;
        #pragma unroll
        for (int k = 0; k < 3; k++) {
            int idx = tid + k*256;
            int r = idx / 6, c = idx % 6;
            int vr = (r & 96) | (8*((r&7)>>1) + 2*((r>>3)&3) + (r&1));
            uint32_t off = vr*128 + ((c ^ (vr&7))<<4);
            cp16(bufb + PM_VH + off, vhp + r*DH + c*8);
            cp16(bufb + PM_VL + off, vlp + r*DH + c*8);
        }
    };

    load_stage(0, sb + PM_OFF_TILE + 0*PM_BUF);
    cp_commit();
    load_stage(1, sb + PM_OFF_TILE + 1*PM_BUF);
    cp_commit();
    __syncthreads();

    float acc[4][3][4];
    #pragma unroll
    for (int hh = 0; hh < 4; hh++)
        #pragma unroll
        for (int nt = 0; nt < 3; nt++)
            #pragma unroll
            for (int p = 0; p < 4; p++) acc[hh][nt][p] = 0.f;

    float macc[4][8];   // register head-mean accumulator (per-thread (q,cj) tile)

    for (int jt = 0; jt < 16; jt++) {
        #pragma unroll
        for (int hh = 0; hh < 4; hh++) {
            const int st = jt*4 + hh;
            if (st + 2 < 64) {
                load_stage(st + 2, sb + PM_OFF_TILE + ((st+2) % 3)*PM_BUF);
                cp_commit();
                cp_wait2();
            } else {
                cp_wait0();
            }
            __syncthreads();
            const uint32_t tb = sb + PM_OFF_TILE + (st % 3)*PM_BUF;
            const char*   tbp = smem + PM_OFF_TILE + (st % 3)*PM_BUF;

            // head-mean accumulation into registers (no sMean RMW)
            #pragma unroll
            for (int k = 0; k < 4; k++) {
                int idx = tid + k*256;
                int q = idx >> 4, cj = idx & 15;
                uint32_t eoff = q*256 + ((cj ^ (q&7))<<4);
                uint4 uh = *reinterpret_cast<const uint4*>(tbp + PM_EH + eoff);
                uint4 ul = *reinterpret_cast<const uint4*>(tbp + PM_EL + eoff);
                float linv = sLinvf[hh*64 + q];
                float2 f0 = __bfloat1622float2(*reinterpret_cast<__nv_bfloat162*>(&uh.x));
                float2 f1 = __bfloat1622float2(*reinterpret_cast<__nv_bfloat162*>(&uh.y));
                float2 f2 = __bfloat1622float2(*reinterpret_cast<__nv_bfloat162*>(&uh.z));
                float2 f3 = __bfloat1622float2(*reinterpret_cast<__nv_bfloat162*>(&uh.w));
                float2 g0 = __bfloat1622float2(*reinterpret_cast<__nv_bfloat162*>(&ul.x));
                float2 g1 = __bfloat1622float2(*reinterpret_cast<__nv_bfloat162*>(&ul.y));
                float2 g2 = __bfloat1622float2(*reinterpret_cast<__nv_bfloat162*>(&ul.z));
                float2 g3 = __bfloat1622float2(*reinterpret_cast<__nv_bfloat162*>(&ul.w));
                if (hh == 0) {
                    macc[k][0] = (f0.x+g0.x)*linv; macc[k][1] = (f0.y+g0.y)*linv;
                    macc[k][2] = (f1.x+g1.x)*linv; macc[k][3] = (f1.y+g1.y)*linv;
                    macc[k][4] = (f2.x+g2.x)*linv; macc[k][5] = (f2.y+g2.y)*linv;
                    macc[k][6] = (f3.x+g3.x)*linv; macc[k][7] = (f3.y+g3.y)*linv;
                } else {
                    macc[k][0] += (f0.x+g0.x)*linv; macc[k][1] += (f0.y+g0.y)*linv;
                    macc[k][2] += (f1.x+g1.x)*linv; macc[k][3] += (f1.y+g1.y)*linv;
                    macc[k][4] += (f2.x+g2.x)*linv; macc[k][5] += (f2.y+g2.y)*linv;
                    macc[k][6] += (f3.x+g3.x)*linv; macc[k][7] += (f3.y+g3.y)*linv;
                }
            }

            #pragma unroll
            for (int ks = 0; ks < 8; ks++) {
                int ra = q0w + (lane & 15);
                int ca = ks*2 + (lane >> 4);
                uint32_t aoff = ra*256 + ((ca ^ (ra&7))<<4);
                uint32_t ahf[4], alf[4];
                ldsm4(tb + PM_EH + aoff, ahf);
                ldsm4(tb + PM_EL + aoff, alf);

                int rb = ks*16 + (lane & 15);
                int cb4 = cV + (lane >> 4);
                uint32_t boff4 = rb*128 + ((cb4 ^ (rb&7))<<4);
                uint32_t bh4[4], bl4[4];
                ldsm4t(tb + PM_VH + boff4, bh4);
                ldsm4t(tb + PM_VL + boff4, bl4);
                int cb2 = cV + 2;
                uint32_t boff2 = rb*128 + ((cb2 ^ (rb&7))<<4);
                uint32_t bh2[2], bl2[2];
                ldsm2t(tb + PM_VH + boff2, bh2);
                ldsm2t(tb + PM_VL + boff2, bl2);

                #pragma unroll
                for (int nt = 0; nt < 2; nt++) {
                    float* a = acc[hh][nt];
                    mma16816(a, ahf, &bh4[nt*2]);
                    mma16816(a, ahf, &bl4[nt*2]);
                    mma16816(a, alf, &bh4[nt*2]);
                }
                {
                    float* a = acc[hh][2];
                    mma16816(a, ahf, bh2);
                    mma16816(a, ahf, bl2);
                    mma16816(a, alf, bh2);
                }
            }

            if (hh == 3) {
                // single sMean write per jt, then de-permuted om write
                #pragma unroll
                for (int k = 0; k < 4; k++) {
                    int idx = tid + k*256;
                    int q = idx >> 4, cj = idx & 15;
                    float* mp = sMean + q*132 + cj*8;
                    float4 m0; m0.x = macc[k][0]; m0.y = macc[k][1]; m0.z = macc[k][2]; m0.w = macc[k][3];
                    float4 m1; m1.x = macc[k][4]; m1.y = macc[k][5]; m1.z = macc[k][6]; m1.w = macc[k][7];
                    *reinterpret_cast<float4*>(mp)     = m0;
                    *reinterpret_cast<float4*>(mp + 4) = m1;
                }
                __syncthreads();
                #pragma unroll
                for (int k = 0; k < 8; k++) {
                    int idx = tid + k*256;
                    int q = idx >> 5, c4 = idx & 31;
                    int g = (c4 >> 3) << 5;
                    int r32 = (4*c4) & 31;
                    int v0 = g + 8*((r32 & 7) >> 1) + 2*(r32 >> 3);
                    float2 m0 = *reinterpret_cast<const float2*>(sMean + q*132 + v0);
                    float2 m1 = *reinterpret_cast<const float2*>(sMean + q*132 + v0 + 8);
                    float4 r;
                    r.x = 0.25f*m0.x; r.y = 0.25f*m0.y;
                    r.z = 0.25f*m1.x; r.w = 0.25f*m1.y;
                    *reinterpret_cast<float4*>(om + (size_t)(b*S + q0 + q)*S + jt*128 + c4*4) = r;
                }
            }
            __syncthreads();
        }
    }

    #pragma unroll
    for (int hh = 0; hh < 4; hh++) {
        const int row0 = q0w + (lane >> 2);
        const float l0 = sLinvf[hh*64 + row0];
        const float l1 = sLinvf[hh*64 + row0 + 8];
        #pragma unroll
        for (int nt = 0; nt < 3; nt++) {
            const int col = hh*48 + wd*24 + nt*8 + (lane & 3)*2;
            float2 o0; o0.x = acc[hh][nt][0]*l0; o0.y = acc[hh][nt][1]*l0;
            float2 o1; o1.x = acc[hh][nt][2]*l1; o1.y = acc[hh][nt][3]*l1;
            *reinterpret_cast<float2*>(g_ctx + (size_t)(b*S + q0 + row0)*D + col)     = o0;
            *reinterpret_cast<float2*>(g_ctx + (size_t)(b*S + q0 + row0 + 8)*D + col) = o1;
        }
    }
}

extern "C" void kernel_launch(void* const* d_in, const int* in_sizes, int n_in,
                              void* d_out, int out_size) {
    (void)in_sizes; (void)n_in; (void)out_size;
    const float* query = (const float*)d_in[0];
    const float* key   = (const float*)d_in[1];
    const float* value = (const float*)d_in[2];
    const int*   mask  = (const int*)  d_in[3];
    const float* bias  = (const float*)d_in[4];
    const float* Wq    = (const float*)d_in[5];
    const float* Wk    = (const float*)d_in[6];
    const float* Wv    = (const float*)d_in[7];
    const float* Wo    = (const float*)d_in[8];

    float* out = (float*)d_out;                 // [B,S,D]
    float* om  = out + B*S*D;                   // [B,S,S] mean weights

    float *pctx;
    cudaGetSymbolAddress((void**)&pctx, g_ctx);

    cudaFuncSetAttribute(logits_mma, cudaFuncAttributeMaxDynamicSharedMemorySize, SMEM_LG);
    cudaFuncSetAttribute(pv_mma,     cudaFuncAttributeMaxDynamicSharedMemorySize, SMEM_PV);

    transpose_w<<<dim3(6,6,4), dim3(32,8)>>>(Wq, Wk, Wv, Wo);
    mbits_kernel<<<(B*S)/8, 256>>>(mask);
    proj3_kernel<<<dim3(256,3), 128>>>(query, key, value);
    logits_mma<<<dim3(B*H, S/64), 256, SMEM_LG>>>(bias);
    pv_mma<<<dim3(B, S/64), 256, SMEM_PV>>>(om);
    proj1_kernel<<<dim3(256,1), 128>>>(pctx, out);
}